// round 1
// baseline (speedup 1.0000x reference)
#include <cuda_runtime.h>

#define BB 2
#define SS 2048
#define EE 2048
#define NH 16
#define NKV 4
#define HD 128
#define WINDOW 1024
#define MROWS (BB*SS)   // 4096

// Scratch (device globals; no allocation allowed)
__device__ float g_Q [MROWS * NH  * HD];   // 33.5 MB  [b,s,h,d]
__device__ float g_K [MROWS * NKV * HD];   //  8.4 MB  [b,s,kvh,d]
__device__ float g_V [MROWS * NKV * HD];   //  8.4 MB
__device__ float g_Ao[MROWS * NH  * HD];   // 33.5 MB  attention output

// ---------------------------------------------------------------------------
// SGEMM NT:  C[M,N] = A[M,K] * B[N,K]^T   (both row-major, K contiguous)
// 128x128 tile, BK=16, 256 threads, 8x8 microtile.
// Requires M%128==0, N%128==0, K%16==0.
// ---------------------------------------------------------------------------
#define GBM 128
#define GBN 128
#define GBK 16

__global__ __launch_bounds__(256) void sgemm_nt(
    const float* __restrict__ A, const float* __restrict__ Bw,
    float* __restrict__ C, int M, int N, int K)
{
    __shared__ float As[GBK][GBM];
    __shared__ float Bs[GBK][GBN];

    const int tid = threadIdx.x;
    const int tx = tid & 15;
    const int ty = tid >> 4;
    const int m0 = blockIdx.x * GBM;
    const int n0 = blockIdx.y * GBN;

    float acc[8][8];
#pragma unroll
    for (int i = 0; i < 8; i++)
#pragma unroll
        for (int j = 0; j < 8; j++) acc[i][j] = 0.f;

    for (int k0 = 0; k0 < K; k0 += GBK) {
#pragma unroll
        for (int t = 0; t < 2; t++) {
            int f   = tid * 2 + t;        // 0..511 float4 units (128 rows x 4)
            int row = f >> 2;
            int col = (f & 3) * 4;
            float4 av = *(const float4*)(A + (size_t)(m0 + row) * K + k0 + col);
            As[col + 0][row] = av.x; As[col + 1][row] = av.y;
            As[col + 2][row] = av.z; As[col + 3][row] = av.w;
            float4 bv = *(const float4*)(Bw + (size_t)(n0 + row) * K + k0 + col);
            Bs[col + 0][row] = bv.x; Bs[col + 1][row] = bv.y;
            Bs[col + 2][row] = bv.z; Bs[col + 3][row] = bv.w;
        }
        __syncthreads();

#pragma unroll
        for (int k = 0; k < GBK; k++) {
            float a[8], b[8];
            *(float4*)&a[0] = *(const float4*)&As[k][ty * 4];
            *(float4*)&a[4] = *(const float4*)&As[k][64 + ty * 4];
            *(float4*)&b[0] = *(const float4*)&Bs[k][tx * 4];
            *(float4*)&b[4] = *(const float4*)&Bs[k][64 + tx * 4];
#pragma unroll
            for (int i = 0; i < 8; i++)
#pragma unroll
                for (int j = 0; j < 8; j++)
                    acc[i][j] += a[i] * b[j];
        }
        __syncthreads();
    }

#pragma unroll
    for (int i = 0; i < 8; i++) {
        int m = m0 + ((i < 4) ? (ty * 4 + i) : (64 + ty * 4 + i - 4));
        float4 v0 = make_float4(acc[i][0], acc[i][1], acc[i][2], acc[i][3]);
        float4 v1 = make_float4(acc[i][4], acc[i][5], acc[i][6], acc[i][7]);
        *(float4*)(C + (size_t)m * N + n0 + tx * 4)      = v0;
        *(float4*)(C + (size_t)m * N + n0 + 64 + tx * 4) = v1;
    }
}

// ---------------------------------------------------------------------------
// RoPE (duplicated-half layout): pairs (d, d+64), cos/sin identical per pair.
// X layout [b*s, nh, 128]. One thread per pair.
// ---------------------------------------------------------------------------
__global__ __launch_bounds__(256) void rope_kernel(
    float* __restrict__ X, const float* __restrict__ cosT,
    const float* __restrict__ sinT, int nh)
{
    int idx = blockIdx.x * blockDim.x + threadIdx.x;   // over MROWS*nh*64
    int d   = idx & 63;
    int t   = idx >> 6;
    int h   = t % nh;
    int bs  = t / nh;
    int s   = bs & (SS - 1);

    float c  = cosT[s * HD + d];
    float sn = sinT[s * HD + d];
    size_t base = ((size_t)bs * nh + h) * HD;
    float x1 = X[base + d];
    float x2 = X[base + d + 64];
    X[base + d]      = x1 * c - x2 * sn;
    X[base + d + 64] = x2 * c + x1 * sn;
}

// ---------------------------------------------------------------------------
// Flash attention, fp32, sliding-window causal (0 <= i-j < WINDOW), GQA.
// BQ=BK=64, 256 threads. K and V share one smem buffer (K: [d][k], V: [k][d]).
// ---------------------------------------------------------------------------
#define BQ 64
#define BKB 64
#define SSTRIDE 66

struct AttnSmem {
    float Qs[HD * BQ];        // [d][q]
    float KV[HD * BKB];       // K phase: [d][k]; V phase: [k][d]
    float Ss[BQ * SSTRIDE];   // scores / probs
    float red [BQ * 4];
    float red2[BQ * 4];
    float mrow[BQ];
    float lrow[BQ];
    float frow[BQ];
};

__global__ __launch_bounds__(256) void attn_kernel(
    const float* __restrict__ Q, const float* __restrict__ K,
    const float* __restrict__ V, float* __restrict__ O)
{
    extern __shared__ float smf[];
    AttnSmem* sm = (AttnSmem*)smf;

    const int tid = threadIdx.x;
    const int qb  = blockIdx.x;
    const int h   = blockIdx.y;
    const int b   = blockIdx.z;
    const int kvh = h >> 2;            // NH/NKV = 4
    const int q0  = qb * BQ;
    const int tq  = tid >> 4;          // 0..15 -> rows tq*4..+3
    const int tx  = tid & 15;          // S cols: tx*4 ; O cols: tx*8
    const int r4  = tid >> 2;          // softmax row
    const int seg = tid & 3;           // softmax segment (16 cols each)

    // Load Q block transposed: Qs[d][r]
#pragma unroll
    for (int it = 0; it < 8; it++) {
        int f  = tid + it * 256;       // 2048 float4 units
        int r  = f >> 5;
        int d4 = (f & 31) << 2;
        float4 v = *(const float4*)(Q + (((size_t)(b * SS + q0 + r)) * NH + h) * HD + d4);
        sm->Qs[(d4 + 0) * BQ + r] = v.x;
        sm->Qs[(d4 + 1) * BQ + r] = v.y;
        sm->Qs[(d4 + 2) * BQ + r] = v.z;
        sm->Qs[(d4 + 3) * BQ + r] = v.w;
    }
    if (tid < BQ) { sm->mrow[tid] = -1e30f; sm->lrow[tid] = 0.f; }

    float oacc[4][8];
#pragma unroll
    for (int i = 0; i < 4; i++)
#pragma unroll
        for (int j = 0; j < 8; j++) oacc[i][j] = 0.f;

    const int kb_lo = (qb >= WINDOW / BKB) ? (qb - WINDOW / BKB) : 0;
    const float scl = 0.08838834764831845f;   // 1/sqrt(128)

    for (int kb = kb_lo; kb <= qb; kb++) {
        const int k0 = kb * BKB;

        // --- load K transposed into KV: [d][k] ---
#pragma unroll
        for (int it = 0; it < 8; it++) {
            int f  = tid + it * 256;
            int r  = f >> 5;
            int d4 = (f & 31) << 2;
            float4 v = *(const float4*)(K + (((size_t)(b * SS + k0 + r)) * NKV + kvh) * HD + d4);
            sm->KV[(d4 + 0) * BKB + r] = v.x;
            sm->KV[(d4 + 1) * BKB + r] = v.y;
            sm->KV[(d4 + 2) * BKB + r] = v.z;
            sm->KV[(d4 + 3) * BKB + r] = v.w;
        }
        __syncthreads();   // (a) K ready; Qs ready (first iter)

        // --- S = Q K^T (4x4 per thread) ---
        float sacc[4][4];
#pragma unroll
        for (int i = 0; i < 4; i++)
#pragma unroll
            for (int j = 0; j < 4; j++) sacc[i][j] = 0.f;

#pragma unroll 4
        for (int d = 0; d < HD; d++) {
            float a[4], bb2[4];
            *(float4*)a   = *(const float4*)&sm->Qs[d * BQ  + tq * 4];
            *(float4*)bb2 = *(const float4*)&sm->KV[d * BKB + tx * 4];
#pragma unroll
            for (int i = 0; i < 4; i++)
#pragma unroll
                for (int j = 0; j < 4; j++)
                    sacc[i][j] += a[i] * bb2[j];
        }

        // mask + scale + store to Ss
#pragma unroll
        for (int i = 0; i < 4; i++) {
            int gi = q0 + tq * 4 + i;
#pragma unroll
            for (int j = 0; j < 4; j++) {
                int gj = k0 + tx * 4 + j;
                int dist = gi - gj;
                float val = (dist >= 0 && dist < WINDOW) ? sacc[i][j] * scl : -1e30f;
                sm->Ss[(tq * 4 + i) * SSTRIDE + tx * 4 + j] = val;
            }
        }
        __syncthreads();   // (b) Ss ready; K reads done -> KV reusable

        // --- load V into KV: [k][d]; overlapped with partial row max ---
#pragma unroll
        for (int it = 0; it < 8; it++) {
            int f  = tid + it * 256;
            int r  = f >> 5;
            int d4 = (f & 31) << 2;
            float4 v = *(const float4*)(V + (((size_t)(b * SS + k0 + r)) * NKV + kvh) * HD + d4);
            *(float4*)&sm->KV[r * HD + d4] = v;
        }
        {
            float mb = -1e30f;
            const float* row = &sm->Ss[r4 * SSTRIDE + seg * 16];
#pragma unroll
            for (int c = 0; c < 16; c++) mb = fmaxf(mb, row[c]);
            sm->red[r4 * 4 + seg] = mb;
        }
        __syncthreads();   // (c) partial maxima ready

        float mB = fmaxf(fmaxf(sm->red[r4 * 4 + 0], sm->red[r4 * 4 + 1]),
                         fmaxf(sm->red[r4 * 4 + 2], sm->red[r4 * 4 + 3]));
        float mold = sm->mrow[r4];
        float mnew = fmaxf(mold, mB);
        {
            float lsum = 0.f;
            float* row = &sm->Ss[r4 * SSTRIDE + seg * 16];
#pragma unroll
            for (int c = 0; c < 16; c++) {
                float p = __expf(row[c] - mnew);
                row[c] = p;
                lsum += p;
            }
            sm->red2[r4 * 4 + seg] = lsum;
        }
        __syncthreads();   // (d) probs + partial sums ready

        if (seg == 0) {
            float fac = __expf(mold - mnew);
            sm->frow[r4] = fac;
            sm->mrow[r4] = mnew;
            sm->lrow[r4] = sm->lrow[r4] * fac +
                sm->red2[r4 * 4 + 0] + sm->red2[r4 * 4 + 1] +
                sm->red2[r4 * 4 + 2] + sm->red2[r4 * 4 + 3];
        }
        __syncthreads();   // (e) stats + V stores visible

        // --- rescale + O += P V ---
        {
            float fr[4];
#pragma unroll
            for (int i = 0; i < 4; i++) fr[i] = sm->frow[tq * 4 + i];
#pragma unroll
            for (int i = 0; i < 4; i++)
#pragma unroll
                for (int j = 0; j < 8; j++) oacc[i][j] *= fr[i];
        }
#pragma unroll 2
        for (int kk = 0; kk < BKB; kk++) {
            float pv[4];
#pragma unroll
            for (int i = 0; i < 4; i++)
                pv[i] = sm->Ss[(tq * 4 + i) * SSTRIDE + kk];
            float vv[8];
            *(float4*)&vv[0] = *(const float4*)&sm->KV[kk * HD + tx * 8];
            *(float4*)&vv[4] = *(const float4*)&sm->KV[kk * HD + tx * 8 + 4];
#pragma unroll
            for (int i = 0; i < 4; i++)
#pragma unroll
                for (int j = 0; j < 8; j++)
                    oacc[i][j] += pv[i] * vv[j];
        }
        __syncthreads();   // (f) protect KV/Ss for next iteration
    }

    // finalize: divide by l, write out
#pragma unroll
    for (int i = 0; i < 4; i++) {
        int r = tq * 4 + i;
        float inv = 1.0f / sm->lrow[r];
        float4 o0 = make_float4(oacc[i][0] * inv, oacc[i][1] * inv,
                                oacc[i][2] * inv, oacc[i][3] * inv);
        float4 o1 = make_float4(oacc[i][4] * inv, oacc[i][5] * inv,
                                oacc[i][6] * inv, oacc[i][7] * inv);
        float* dst = O + (((size_t)(b * SS + q0 + r)) * NH + h) * HD + tx * 8;
        *(float4*)dst       = o0;
        *(float4*)(dst + 4) = o1;
    }
}

// ---------------------------------------------------------------------------
// Launch
// ---------------------------------------------------------------------------
extern "C" void kernel_launch(void* const* d_in, const int* in_sizes, int n_in,
                              void* d_out, int out_size)
{
    const float* x    = (const float*)d_in[0];
    const float* cosT = (const float*)d_in[1];
    const float* sinT = (const float*)d_in[2];
    const float* Wq   = (const float*)d_in[3];
    const float* Wk   = (const float*)d_in[4];
    const float* Wv   = (const float*)d_in[5];
    const float* Wo   = (const float*)d_in[6];
    float* out = (float*)d_out;

    void *pQ, *pK, *pV, *pA;
    cudaGetSymbolAddress(&pQ, g_Q);
    cudaGetSymbolAddress(&pK, g_K);
    cudaGetSymbolAddress(&pV, g_V);
    cudaGetSymbolAddress(&pA, g_Ao);
    float* Qp = (float*)pQ;
    float* Kp = (float*)pK;
    float* Vp = (float*)pV;
    float* Ap = (float*)pA;

    // Projections
    sgemm_nt<<<dim3(MROWS / GBM, (NH  * HD) / GBN), 256>>>(x, Wq, Qp, MROWS, NH  * HD, EE);
    sgemm_nt<<<dim3(MROWS / GBM, (NKV * HD) / GBN), 256>>>(x, Wk, Kp, MROWS, NKV * HD, EE);
    sgemm_nt<<<dim3(MROWS / GBM, (NKV * HD) / GBN), 256>>>(x, Wv, Vp, MROWS, NKV * HD, EE);

    // RoPE
    rope_kernel<<<(MROWS * NH  * 64) / 256, 256>>>(Qp, cosT, sinT, NH);
    rope_kernel<<<(MROWS * NKV * 64) / 256, 256>>>(Kp, cosT, sinT, NKV);

    // Attention
    int smem = (int)sizeof(AttnSmem);
    cudaFuncSetAttribute(attn_kernel, cudaFuncAttributeMaxDynamicSharedMemorySize, smem);
    attn_kernel<<<dim3(SS / BQ, NH, BB), 256, smem>>>(Qp, Kp, Vp, Ap);

    // Output projection
    sgemm_nt<<<dim3(MROWS / GBM, EE / GBN), 256>>>(Ap, Wo, out, MROWS, EE, EE);
}

// round 6
// speedup vs baseline: 1.1468x; 1.1468x over previous
#include <cuda_runtime.h>
#include <cstdint>

#define BB 2
#define SS 2048
#define EE 2048
#define NH 16
#define NKV 4
#define HD 128
#define WINDOW 1024
#define MROWS (BB*SS)   // 4096

// ---------------- scratch (device globals) ----------------
__device__ float g_Q [MROWS * NH  * HD];
__device__ float g_K [MROWS * NKV * HD];
__device__ float g_V [MROWS * NKV * HD];
__device__ float g_Ao[MROWS * NH  * HD];
__device__ float g_Xr[MROWS * EE];          // tf32-rounded x
__device__ float g_Wq[NH  * HD * EE];
__device__ float g_Wk[NKV * HD * EE];
__device__ float g_Wv[NKV * HD * EE];
__device__ float g_Wo[EE * EE];

// ---------------- helpers ----------------
__device__ __forceinline__ uint32_t smem_u32(const void* p) {
    uint32_t a;
    asm("{ .reg .u64 t; cvta.to.shared.u64 t, %1; cvt.u32.u64 %0, t; }" : "=r"(a) : "l"(p));
    return a;
}
__device__ __forceinline__ void cp16(uint32_t dst, const void* src) {
    asm volatile("cp.async.cg.shared.global [%0], [%1], 16;" :: "r"(dst), "l"(src) : "memory");
}
__device__ __forceinline__ float tf32r(float x) {
    uint32_t u; asm("cvt.rna.tf32.f32 %0, %1;" : "=r"(u) : "f"(x));
    return __uint_as_float(u);
}
__device__ __forceinline__ uint32_t swz(uint32_t off) {   // SW128 (Swizzle<3,4,3>)
    return off ^ ((off >> 3) & 0x70);
}
__device__ __forceinline__ void ldsm4(uint32_t& r0, uint32_t& r1, uint32_t& r2,
                                      uint32_t& r3, uint32_t addr) {
    asm volatile("ldmatrix.sync.aligned.m8n8.x4.shared.b16 {%0,%1,%2,%3}, [%4];"
                 : "=r"(r0), "=r"(r1), "=r"(r2), "=r"(r3) : "r"(addr));
}
__device__ __forceinline__ void mma_tf32(float& c0, float& c1, float& c2, float& c3,
                                         uint32_t a0, uint32_t a1, uint32_t a2, uint32_t a3,
                                         uint32_t b0, uint32_t b1) {
    asm volatile("mma.sync.aligned.m16n8k8.row.col.f32.tf32.tf32.f32 "
                 "{%0,%1,%2,%3}, {%4,%5,%6,%7}, {%8,%9}, {%0,%1,%2,%3};"
                 : "+f"(c0), "+f"(c1), "+f"(c2), "+f"(c3)
                 : "r"(a0), "r"(a1), "r"(a2), "r"(a3), "r"(b0), "r"(b1));
}

// ---------------------------------------------------------------------------
// Round fp32 -> tf32(rna)
// ---------------------------------------------------------------------------
__global__ __launch_bounds__(256) void round_tf32_kernel(const float* __restrict__ in,
                                                         float* __restrict__ out) {
    int i = blockIdx.x * blockDim.x + threadIdx.x;
    float4 v = ((const float4*)in)[i];
    v.x = tf32r(v.x); v.y = tf32r(v.y); v.z = tf32r(v.z); v.w = tf32r(v.w);
    ((float4*)out)[i] = v;
}

// ---------------------------------------------------------------------------
// TF32 mma.sync GEMM:  C[M,N] = A[M,K] * B[N,K]^T, fp32 out.
// CTA tile 128x128, K-chunk 32, 4-stage cp.async pipeline, 256 threads.
// Warp grid 2(m) x 4(n); warp tile 64x32. Requires M%128==0, N%128==0, K%32==0.
// ---------------------------------------------------------------------------
#define TM 128
#define TN 128
#define KC 32
#define NSTAGE 4
#define A_BYTES (TM*KC*4)            // 16384
#define STAGE_BYTES (A_BYTES*2)      // 32768 (A + B)
#define GEMM_DYN (NSTAGE*STAGE_BYTES + 1024)

__device__ __forceinline__ void gemm_load_chunk(
    uint32_t stageBase, const float* __restrict__ A, const float* __restrict__ B,
    int m0, int n0, int k0, int K, int tid)
{
#pragma unroll
    for (int i = 0; i < 8; i++) {
        int id = tid + i * 256;           // 0..2047
        int row = (id >> 3) & 127;
        int c16 = id & 7;
        uint32_t off = (uint32_t)(row * 128 + c16 * 16);
        if (id < 1024) {
            cp16(stageBase + swz(off), A + (size_t)(m0 + row) * K + k0 + c16 * 4);
        } else {
            cp16(stageBase + A_BYTES + swz(off), B + (size_t)(n0 + row) * K + k0 + c16 * 4);
        }
    }
}

__global__ __launch_bounds__(256, 1) void gemm_tf32(
    const float* __restrict__ A, const float* __restrict__ B,
    float* __restrict__ C, int N, int K)
{
    extern __shared__ char dynsmem[];
    uint32_t base = (smem_u32(dynsmem) + 1023) & ~1023u;

    const int tid  = threadIdx.x;
    const int wid  = tid >> 5;
    const int lane = tid & 31;
    const int wm   = wid & 1;            // 0..1
    const int wn   = wid >> 1;           // 0..3
    const int grp  = lane >> 2;
    const int tig  = lane & 3;
    const int t8    = lane & 7;
    const int which = lane >> 3;         // 0..3 (ldmatrix matrix index)
    const int m0 = blockIdx.x * TM;
    const int n0 = blockIdx.y * TN;
    const int NC = K / KC;

    float acc[4][4][4];
#pragma unroll
    for (int a = 0; a < 4; a++)
#pragma unroll
        for (int b = 0; b < 4; b++)
#pragma unroll
            for (int c = 0; c < 4; c++) acc[a][b][c] = 0.f;

    // ldmatrix per-thread row/col offsets (within tile, bytes), before k-step col add
    uint32_t aRowOff[4], bRowOff[2];
#pragma unroll
    for (int mt = 0; mt < 4; mt++)
        aRowOff[mt] = (uint32_t)((wm * 64 + mt * 16 + (which & 1) * 8 + t8) * 128 + (which >> 1) * 16);
#pragma unroll
    for (int p = 0; p < 2; p++)
        bRowOff[p] = (uint32_t)((wn * 32 + p * 16 + (which >> 1) * 8 + t8) * 128 + (which & 1) * 16);

    // ---- prologue ----
#pragma unroll
    for (int pc = 0; pc < NSTAGE - 1; pc++) {
        gemm_load_chunk(base + pc * STAGE_BYTES, A, B, m0, n0, pc * KC, K, tid);
        asm volatile("cp.async.commit_group;" ::: "memory");
    }

    // ---- main loop ----
    for (int c = 0; c < NC; c++) {
        asm volatile("cp.async.wait_group %0;" :: "n"(NSTAGE - 2) : "memory");
        __syncthreads();

        int lc = c + NSTAGE - 1;
        if (lc < NC)
            gemm_load_chunk(base + (lc % NSTAGE) * STAGE_BYTES, A, B, m0, n0, lc * KC, K, tid);
        asm volatile("cp.async.commit_group;" ::: "memory");

        uint32_t aB = base + (c % NSTAGE) * STAGE_BYTES;
        uint32_t bB = aB + A_BYTES;

#pragma unroll
        for (int ks = 0; ks < 4; ks++) {
            uint32_t kcol = (uint32_t)(ks * 32);
            uint32_t af[4][4], bf[2][4];
#pragma unroll
            for (int mt = 0; mt < 4; mt++) {
                uint32_t off = aRowOff[mt] + kcol;
                ldsm4(af[mt][0], af[mt][1], af[mt][2], af[mt][3], aB + swz(off));
            }
#pragma unroll
            for (int p = 0; p < 2; p++) {
                uint32_t off = bRowOff[p] + kcol;
                ldsm4(bf[p][0], bf[p][1], bf[p][2], bf[p][3], bB + swz(off));
            }
#pragma unroll
            for (int mt = 0; mt < 4; mt++) {
#pragma unroll
                for (int p = 0; p < 2; p++) {
                    mma_tf32(acc[mt][2*p][0], acc[mt][2*p][1], acc[mt][2*p][2], acc[mt][2*p][3],
                             af[mt][0], af[mt][1], af[mt][2], af[mt][3],
                             bf[p][0], bf[p][1]);
                    mma_tf32(acc[mt][2*p+1][0], acc[mt][2*p+1][1], acc[mt][2*p+1][2], acc[mt][2*p+1][3],
                             af[mt][0], af[mt][1], af[mt][2], af[mt][3],
                             bf[p][2], bf[p][3]);
                }
            }
        }
    }

    // ---- epilogue ----
#pragma unroll
    for (int mt = 0; mt < 4; mt++) {
        int rbase = m0 + wm * 64 + mt * 16 + grp;
#pragma unroll
        for (int nt = 0; nt < 4; nt++) {
            int col = n0 + wn * 32 + nt * 8 + 2 * tig;
            float* d0 = C + (size_t)rbase * N + col;
            float* d1 = C + (size_t)(rbase + 8) * N + col;
            d0[0] = acc[mt][nt][0]; d0[1] = acc[mt][nt][1];
            d1[0] = acc[mt][nt][2]; d1[1] = acc[mt][nt][3];
        }
    }
}

// ---------------------------------------------------------------------------
// RoPE (duplicated-half layout)
// ---------------------------------------------------------------------------
__global__ __launch_bounds__(256) void rope_kernel(
    float* __restrict__ X, const float* __restrict__ cosT,
    const float* __restrict__ sinT, int nh)
{
    int idx = blockIdx.x * blockDim.x + threadIdx.x;
    int d   = idx & 63;
    int t   = idx >> 6;
    int h   = t % nh;
    int bs  = t / nh;
    int s   = bs & (SS - 1);

    float c  = cosT[s * HD + d];
    float sn = sinT[s * HD + d];
    size_t base = ((size_t)bs * nh + h) * HD;
    float x1 = X[base + d];
    float x2 = X[base + d + 64];
    X[base + d]      = x1 * c - x2 * sn;
    X[base + d + 64] = x2 * c + x1 * sn;
}

// ---------------------------------------------------------------------------
// Flash attention, fp32, sliding-window causal, GQA.
// ---------------------------------------------------------------------------
#define BQ 64
#define BKB 64
#define SSTRIDE 66

struct AttnSmem {
    float Qs[HD * BQ];
    float KV[HD * BKB];
    float Ss[BQ * SSTRIDE];
    float red [BQ * 4];
    float red2[BQ * 4];
    float mrow[BQ];
    float lrow[BQ];
    float frow[BQ];
};

__global__ __launch_bounds__(256) void attn_kernel(
    const float* __restrict__ Q, const float* __restrict__ K,
    const float* __restrict__ V, float* __restrict__ O)
{
    extern __shared__ float smf[];
    AttnSmem* sm = (AttnSmem*)smf;

    const int tid = threadIdx.x;
    const int qb  = blockIdx.x;
    const int h   = blockIdx.y;
    const int b   = blockIdx.z;
    const int kvh = h >> 2;
    const int q0  = qb * BQ;
    const int tq  = tid >> 4;
    const int tx  = tid & 15;
    const int r4  = tid >> 2;
    const int seg = tid & 3;

#pragma unroll
    for (int it = 0; it < 8; it++) {
        int f  = tid + it * 256;
        int r  = f >> 5;
        int d4 = (f & 31) << 2;
        float4 v = *(const float4*)(Q + (((size_t)(b * SS + q0 + r)) * NH + h) * HD + d4);
        sm->Qs[(d4 + 0) * BQ + r] = v.x;
        sm->Qs[(d4 + 1) * BQ + r] = v.y;
        sm->Qs[(d4 + 2) * BQ + r] = v.z;
        sm->Qs[(d4 + 3) * BQ + r] = v.w;
    }
    if (tid < BQ) { sm->mrow[tid] = -1e30f; sm->lrow[tid] = 0.f; }

    float oacc[4][8];
#pragma unroll
    for (int i = 0; i < 4; i++)
#pragma unroll
        for (int j = 0; j < 8; j++) oacc[i][j] = 0.f;

    const int kb_lo = (qb >= WINDOW / BKB) ? (qb - WINDOW / BKB) : 0;
    const float scl = 0.08838834764831845f;

    for (int kb = kb_lo; kb <= qb; kb++) {
        const int k0 = kb * BKB;

#pragma unroll
        for (int it = 0; it < 8; it++) {
            int f  = tid + it * 256;
            int r  = f >> 5;
            int d4 = (f & 31) << 2;
            float4 v = *(const float4*)(K + (((size_t)(b * SS + k0 + r)) * NKV + kvh) * HD + d4);
            sm->KV[(d4 + 0) * BKB + r] = v.x;
            sm->KV[(d4 + 1) * BKB + r] = v.y;
            sm->KV[(d4 + 2) * BKB + r] = v.z;
            sm->KV[(d4 + 3) * BKB + r] = v.w;
        }
        __syncthreads();

        float sacc[4][4];
#pragma unroll
        for (int i = 0; i < 4; i++)
#pragma unroll
            for (int j = 0; j < 4; j++) sacc[i][j] = 0.f;

#pragma unroll 4
        for (int d = 0; d < HD; d++) {
            float a[4], bb2[4];
            *(float4*)a   = *(const float4*)&sm->Qs[d * BQ  + tq * 4];
            *(float4*)bb2 = *(const float4*)&sm->KV[d * BKB + tx * 4];
#pragma unroll
            for (int i = 0; i < 4; i++)
#pragma unroll
                for (int j = 0; j < 4; j++)
                    sacc[i][j] += a[i] * bb2[j];
        }

#pragma unroll
        for (int i = 0; i < 4; i++) {
            int gi = q0 + tq * 4 + i;
#pragma unroll
            for (int j = 0; j < 4; j++) {
                int gj = k0 + tx * 4 + j;
                int dist = gi - gj;
                float val = (dist >= 0 && dist < WINDOW) ? sacc[i][j] * scl : -1e30f;
                sm->Ss[(tq * 4 + i) * SSTRIDE + tx * 4 + j] = val;
            }
        }
        __syncthreads();

#pragma unroll
        for (int it = 0; it < 8; it++) {
            int f  = tid + it * 256;
            int r  = f >> 5;
            int d4 = (f & 31) << 2;
            float4 v = *(const float4*)(V + (((size_t)(b * SS + k0 + r)) * NKV + kvh) * HD + d4);
            *(float4*)&sm->KV[r * HD + d4] = v;
        }
        {
            float mb = -1e30f;
            const float* row = &sm->Ss[r4 * SSTRIDE + seg * 16];
#pragma unroll
            for (int c = 0; c < 16; c++) mb = fmaxf(mb, row[c]);
            sm->red[r4 * 4 + seg] = mb;
        }
        __syncthreads();

        float mB = fmaxf(fmaxf(sm->red[r4 * 4 + 0], sm->red[r4 * 4 + 1]),
                         fmaxf(sm->red[r4 * 4 + 2], sm->red[r4 * 4 + 3]));
        float mold = sm->mrow[r4];
        float mnew = fmaxf(mold, mB);
        {
            float lsum = 0.f;
            float* row = &sm->Ss[r4 * SSTRIDE + seg * 16];
#pragma unroll
            for (int c = 0; c < 16; c++) {
                float p = __expf(row[c] - mnew);
                row[c] = p;
                lsum += p;
            }
            sm->red2[r4 * 4 + seg] = lsum;
        }
        __syncthreads();

        if (seg == 0) {
            float fac = __expf(mold - mnew);
            sm->frow[r4] = fac;
            sm->mrow[r4] = mnew;
            sm->lrow[r4] = sm->lrow[r4] * fac +
                sm->red2[r4 * 4 + 0] + sm->red2[r4 * 4 + 1] +
                sm->red2[r4 * 4 + 2] + sm->red2[r4 * 4 + 3];
        }
        __syncthreads();

        {
            float fr[4];
#pragma unroll
            for (int i = 0; i < 4; i++) fr[i] = sm->frow[tq * 4 + i];
#pragma unroll
            for (int i = 0; i < 4; i++)
#pragma unroll
                for (int j = 0; j < 8; j++) oacc[i][j] *= fr[i];
        }
#pragma unroll 2
        for (int kk = 0; kk < BKB; kk++) {
            float pv[4];
#pragma unroll
            for (int i = 0; i < 4; i++)
                pv[i] = sm->Ss[(tq * 4 + i) * SSTRIDE + kk];
            float vv[8];
            *(float4*)&vv[0] = *(const float4*)&sm->KV[kk * HD + tx * 8];
            *(float4*)&vv[4] = *(const float4*)&sm->KV[kk * HD + tx * 8 + 4];
#pragma unroll
            for (int i = 0; i < 4; i++)
#pragma unroll
                for (int j = 0; j < 8; j++)
                    oacc[i][j] += pv[i] * vv[j];
        }
        __syncthreads();
    }

#pragma unroll
    for (int i = 0; i < 4; i++) {
        int r = tq * 4 + i;
        float inv = 1.0f / sm->lrow[r];
        float4 o0 = make_float4(tf32r(oacc[i][0] * inv), tf32r(oacc[i][1] * inv),
                                tf32r(oacc[i][2] * inv), tf32r(oacc[i][3] * inv));
        float4 o1 = make_float4(tf32r(oacc[i][4] * inv), tf32r(oacc[i][5] * inv),
                                tf32r(oacc[i][6] * inv), tf32r(oacc[i][7] * inv));
        float* dst = O + (((size_t)(b * SS + q0 + r)) * NH + h) * HD + tx * 8;
        *(float4*)dst       = o0;
        *(float4*)(dst + 4) = o1;
    }
}

// ---------------------------------------------------------------------------
// Launch
// ---------------------------------------------------------------------------
extern "C" void kernel_launch(void* const* d_in, const int* in_sizes, int n_in,
                              void* d_out, int out_size)
{
    const float* x    = (const float*)d_in[0];
    const float* cosT = (const float*)d_in[1];
    const float* sinT = (const float*)d_in[2];
    const float* Wq   = (const float*)d_in[3];
    const float* Wk   = (const float*)d_in[4];
    const float* Wv   = (const float*)d_in[5];
    const float* Wo   = (const float*)d_in[6];
    float* out = (float*)d_out;

    void *pQ, *pK, *pV, *pA, *pXr, *pWq, *pWk, *pWv, *pWo;
    cudaGetSymbolAddress(&pQ, g_Q);
    cudaGetSymbolAddress(&pK, g_K);
    cudaGetSymbolAddress(&pV, g_V);
    cudaGetSymbolAddress(&pA, g_Ao);
    cudaGetSymbolAddress(&pXr, g_Xr);
    cudaGetSymbolAddress(&pWq, g_Wq);
    cudaGetSymbolAddress(&pWk, g_Wk);
    cudaGetSymbolAddress(&pWv, g_Wv);
    cudaGetSymbolAddress(&pWo, g_Wo);
    float* Qp = (float*)pQ;   float* Kp = (float*)pK;
    float* Vp = (float*)pV;   float* Ap = (float*)pA;
    float* Xr = (float*)pXr;
    float* Wqr = (float*)pWq; float* Wkr = (float*)pWk;
    float* Wvr = (float*)pWv; float* Wor = (float*)pWo;

    // Round inputs to tf32 (rna)
    round_tf32_kernel<<<(MROWS * EE / 4) / 256, 256>>>(x, Xr);
    round_tf32_kernel<<<(NH * HD * EE / 4) / 256, 256>>>(Wq, Wqr);
    round_tf32_kernel<<<(NKV * HD * EE / 4) / 256, 256>>>(Wk, Wkr);
    round_tf32_kernel<<<(NKV * HD * EE / 4) / 256, 256>>>(Wv, Wvr);
    round_tf32_kernel<<<(EE * EE / 4) / 256, 256>>>(Wo, Wor);

    // Projections (tf32 mma.sync)
    cudaFuncSetAttribute(gemm_tf32, cudaFuncAttributeMaxDynamicSharedMemorySize, GEMM_DYN);
    gemm_tf32<<<dim3(MROWS / TM, (NH  * HD) / TN), 256, GEMM_DYN>>>(Xr, Wqr, Qp, NH  * HD, EE);
    gemm_tf32<<<dim3(MROWS / TM, (NKV * HD) / TN), 256, GEMM_DYN>>>(Xr, Wkr, Kp, NKV * HD, EE);
    gemm_tf32<<<dim3(MROWS / TM, (NKV * HD) / TN), 256, GEMM_DYN>>>(Xr, Wvr, Vp, NKV * HD, EE);

    // RoPE
    rope_kernel<<<(MROWS * NH  * 64) / 256, 256>>>(Qp, cosT, sinT, NH);
    rope_kernel<<<(MROWS * NKV * 64) / 256, 256>>>(Kp, cosT, sinT, NKV);

    // Attention (fp32)
    int smem = (int)sizeof(AttnSmem);
    cudaFuncSetAttribute(attn_kernel, cudaFuncAttributeMaxDynamicSharedMemorySize, smem);
    attn_kernel<<<dim3(SS / BQ, NH, BB), 256, smem>>>(Qp, Kp, Vp, Ap);

    // Output projection
    gemm_tf32<<<dim3(MROWS / TM, EE / TN), 256, GEMM_DYN>>>(Ap, Wor, out, EE, EE);
}

// round 10
// speedup vs baseline: 2.1568x; 1.8807x over previous
#include <cuda_runtime.h>
#include <cuda_fp16.h>
#include <cstdint>

#define BB 2
#define SS 2048
#define EE 2048
#define NH 16
#define NKV 4
#define HD 128
#define WINDOW 1024
#define MROWS (BB*SS)   // 4096

// ---------------- scratch (device globals) ----------------
__device__ float  g_Q [MROWS * NH  * HD];
__device__ float  g_K [MROWS * NKV * HD];
__device__ float  g_V [MROWS * NKV * HD];
__device__ __half g_Aoh[MROWS * NH  * HD];   // attention out, fp16
__device__ __half g_Xh [MROWS * EE];         // fp16 x
__device__ __half g_Wqh[NH  * HD * EE];
__device__ __half g_Wkh[NKV * HD * EE];
__device__ __half g_Wvh[NKV * HD * EE];
__device__ __half g_Woh[EE * EE];

// ---------------- helpers ----------------
__device__ __forceinline__ uint32_t smem_u32(const void* p) {
    uint32_t a;
    asm("{ .reg .u64 t; cvta.to.shared.u64 t, %1; cvt.u32.u64 %0, t; }" : "=r"(a) : "l"(p));
    return a;
}
__device__ __forceinline__ void cp16(uint32_t dst, const void* src) {
    asm volatile("cp.async.cg.shared.global [%0], [%1], 16;" :: "r"(dst), "l"(src) : "memory");
}
__device__ __forceinline__ uint32_t swz(uint32_t off) {   // SW128 (Swizzle<3,4,3>)
    return off ^ ((off >> 3) & 0x70);
}
__device__ __forceinline__ void ldsm4(uint32_t& r0, uint32_t& r1, uint32_t& r2,
                                      uint32_t& r3, uint32_t addr) {
    asm volatile("ldmatrix.sync.aligned.m8n8.x4.shared.b16 {%0,%1,%2,%3}, [%4];"
                 : "=r"(r0), "=r"(r1), "=r"(r2), "=r"(r3) : "r"(addr));
}
__device__ __forceinline__ void mma_fp16(float& c0, float& c1, float& c2, float& c3,
                                         uint32_t a0, uint32_t a1, uint32_t a2, uint32_t a3,
                                         uint32_t b0, uint32_t b1) {
    asm volatile("mma.sync.aligned.m16n8k16.row.col.f32.f16.f16.f32 "
                 "{%0,%1,%2,%3}, {%4,%5,%6,%7}, {%8,%9}, {%0,%1,%2,%3};"
                 : "+f"(c0), "+f"(c1), "+f"(c2), "+f"(c3)
                 : "r"(a0), "r"(a1), "r"(a2), "r"(a3), "r"(b0), "r"(b1));
}

// ---------------------------------------------------------------------------
// Convert fp32 -> fp16 (rn)
// ---------------------------------------------------------------------------
__global__ __launch_bounds__(256) void conv_fp16_kernel(const float* __restrict__ in,
                                                        __half* __restrict__ out) {
    int i = blockIdx.x * blockDim.x + threadIdx.x;   // one float4 per thread
    float4 v = ((const float4*)in)[i];
    __half2 h0 = __floats2half2_rn(v.x, v.y);
    __half2 h1 = __floats2half2_rn(v.z, v.w);
    ((__half2*)out)[i * 2]     = h0;
    ((__half2*)out)[i * 2 + 1] = h1;
}

// ---------------------------------------------------------------------------
// FP16 mma.sync GEMM:  C[M,N] = A[M,K] * B[N,K]^T, fp32 out.
// CTA tile 128x128, K-chunk 64 (rows 128B), 3-stage cp.async, 256 threads.
// Warp grid 2(m) x 4(n); warp tile 64x32. Requires M%128==0, N%128==0, K%64==0.
// ---------------------------------------------------------------------------
#define TM 128
#define TN 128
#define KC 64
#define NSTAGE 3
#define A_BYTES (TM*KC*2)            // 16384
#define STAGE_BYTES (A_BYTES*2)      // 32768 (A + B)
#define GEMM_DYN (NSTAGE*STAGE_BYTES + 1024)

__device__ __forceinline__ void gemm_load_chunk(
    uint32_t stageBase, const __half* __restrict__ A, const __half* __restrict__ B,
    int m0, int n0, int k0, int K, int tid)
{
#pragma unroll
    for (int i = 0; i < 8; i++) {
        int id = tid + i * 256;           // 0..2047
        int row = (id >> 3) & 127;
        int c16 = id & 7;
        uint32_t off = (uint32_t)(row * 128 + c16 * 16);
        if (id < 1024) {
            cp16(stageBase + swz(off), A + (size_t)(m0 + row) * K + k0 + c16 * 8);
        } else {
            cp16(stageBase + A_BYTES + swz(off), B + (size_t)(n0 + row) * K + k0 + c16 * 8);
        }
    }
}

__global__ __launch_bounds__(256, 2) void gemm_fp16(
    const __half* __restrict__ A, const __half* __restrict__ B,
    float* __restrict__ C, int N, int K)
{
    extern __shared__ char dynsmem[];
    uint32_t base = (smem_u32(dynsmem) + 1023) & ~1023u;

    const int tid  = threadIdx.x;
    const int wid  = tid >> 5;
    const int lane = tid & 31;
    const int wm   = wid & 1;            // 0..1
    const int wn   = wid >> 1;           // 0..3
    const int grp  = lane >> 2;
    const int tig  = lane & 3;
    const int t8    = lane & 7;
    const int which = lane >> 3;         // 0..3 (ldmatrix matrix index)
    const int m0 = blockIdx.x * TM;
    const int n0 = blockIdx.y * TN;
    const int NC = K / KC;

    float acc[4][4][4];
#pragma unroll
    for (int a = 0; a < 4; a++)
#pragma unroll
        for (int b = 0; b < 4; b++)
#pragma unroll
            for (int c = 0; c < 4; c++) acc[a][b][c] = 0.f;

    // ldmatrix per-thread offsets (bytes within tile). 16B column = 8 halves (k8).
    // A: rows via (which&1), k-16B via (which>>1)   -> a0..a3 = m16n8k16 A frag order
    // B: rows via (which>>1), k-16B via (which&1)   -> (r0,r1)=n8 tile lo (k-lo,k-hi),
    //                                                  (r2,r3)=n8 tile hi
    uint32_t aRowOff[4], bRowOff[2];
#pragma unroll
    for (int mt = 0; mt < 4; mt++)
        aRowOff[mt] = (uint32_t)((wm * 64 + mt * 16 + (which & 1) * 8 + t8) * 128 + (which >> 1) * 16);
#pragma unroll
    for (int p = 0; p < 2; p++)
        bRowOff[p] = (uint32_t)((wn * 32 + p * 16 + (which >> 1) * 8 + t8) * 128 + (which & 1) * 16);

    // ---- prologue ----
#pragma unroll
    for (int pc = 0; pc < NSTAGE - 1; pc++) {
        gemm_load_chunk(base + pc * STAGE_BYTES, A, B, m0, n0, pc * KC, K, tid);
        asm volatile("cp.async.commit_group;" ::: "memory");
    }

    // ---- main loop ----
    for (int c = 0; c < NC; c++) {
        asm volatile("cp.async.wait_group %0;" :: "n"(NSTAGE - 2) : "memory");
        __syncthreads();

        int lc = c + NSTAGE - 1;
        if (lc < NC)
            gemm_load_chunk(base + (lc % NSTAGE) * STAGE_BYTES, A, B, m0, n0, lc * KC, K, tid);
        asm volatile("cp.async.commit_group;" ::: "memory");

        uint32_t aB = base + (c % NSTAGE) * STAGE_BYTES;
        uint32_t bB = aB + A_BYTES;

#pragma unroll
        for (int ks = 0; ks < 4; ks++) {          // 4 x k16 per 64-chunk
            uint32_t kbyte = (uint32_t)(ks * 32); // k16 = 32 bytes
            uint32_t af[4][4], bf[2][4];
#pragma unroll
            for (int mt = 0; mt < 4; mt++) {
                uint32_t off = aRowOff[mt] + kbyte;
                ldsm4(af[mt][0], af[mt][1], af[mt][2], af[mt][3], aB + swz(off));
            }
#pragma unroll
            for (int p = 0; p < 2; p++) {
                uint32_t off = bRowOff[p] + kbyte;
                ldsm4(bf[p][0], bf[p][1], bf[p][2], bf[p][3], bB + swz(off));
            }
#pragma unroll
            for (int mt = 0; mt < 4; mt++) {
#pragma unroll
                for (int p = 0; p < 2; p++) {
                    mma_fp16(acc[mt][2*p][0], acc[mt][2*p][1], acc[mt][2*p][2], acc[mt][2*p][3],
                             af[mt][0], af[mt][1], af[mt][2], af[mt][3],
                             bf[p][0], bf[p][1]);
                    mma_fp16(acc[mt][2*p+1][0], acc[mt][2*p+1][1], acc[mt][2*p+1][2], acc[mt][2*p+1][3],
                             af[mt][0], af[mt][1], af[mt][2], af[mt][3],
                             bf[p][2], bf[p][3]);
                }
            }
        }
    }

    // ---- epilogue ----
#pragma unroll
    for (int mt = 0; mt < 4; mt++) {
        int rbase = m0 + wm * 64 + mt * 16 + grp;
#pragma unroll
        for (int nt = 0; nt < 4; nt++) {
            int col = n0 + wn * 32 + nt * 8 + 2 * tig;
            float* d0 = C + (size_t)rbase * N + col;
            float* d1 = C + (size_t)(rbase + 8) * N + col;
            d0[0] = acc[mt][nt][0]; d0[1] = acc[mt][nt][1];
            d1[0] = acc[mt][nt][2]; d1[1] = acc[mt][nt][3];
        }
    }
}

// ---------------------------------------------------------------------------
// RoPE (duplicated-half layout), fp32 in-place
// ---------------------------------------------------------------------------
__global__ __launch_bounds__(256) void rope_kernel(
    float* __restrict__ X, const float* __restrict__ cosT,
    const float* __restrict__ sinT, int nh)
{
    int idx = blockIdx.x * blockDim.x + threadIdx.x;
    int d   = idx & 63;
    int t   = idx >> 6;
    int h   = t % nh;
    int bs  = t / nh;
    int s   = bs & (SS - 1);

    float c  = cosT[s * HD + d];
    float sn = sinT[s * HD + d];
    size_t base = ((size_t)bs * nh + h) * HD;
    float x1 = X[base + d];
    float x2 = X[base + d + 64];
    X[base + d]      = x1 * c - x2 * sn;
    X[base + d + 64] = x2 * c + x1 * sn;
}

// ---------------------------------------------------------------------------
// Flash attention, fp32, sliding-window causal, GQA. Output stored fp16.
// ---------------------------------------------------------------------------
#define BQ 64
#define BKB 64
#define SSTRIDE 66

struct AttnSmem {
    float Qs[HD * BQ];
    float KV[HD * BKB];
    float Ss[BQ * SSTRIDE];
    float red [BQ * 4];
    float red2[BQ * 4];
    float mrow[BQ];
    float lrow[BQ];
    float frow[BQ];
};

__global__ __launch_bounds__(256) void attn_kernel(
    const float* __restrict__ Q, const float* __restrict__ K,
    const float* __restrict__ V, __half* __restrict__ O)
{
    extern __shared__ float smf[];
    AttnSmem* sm = (AttnSmem*)smf;

    const int tid = threadIdx.x;
    const int qb  = blockIdx.x;
    const int h   = blockIdx.y;
    const int b   = blockIdx.z;
    const int kvh = h >> 2;
    const int q0  = qb * BQ;
    const int tq  = tid >> 4;
    const int tx  = tid & 15;
    const int r4  = tid >> 2;
    const int seg = tid & 3;

#pragma unroll
    for (int it = 0; it < 8; it++) {
        int f  = tid + it * 256;
        int r  = f >> 5;
        int d4 = (f & 31) << 2;
        float4 v = *(const float4*)(Q + (((size_t)(b * SS + q0 + r)) * NH + h) * HD + d4);
        sm->Qs[(d4 + 0) * BQ + r] = v.x;
        sm->Qs[(d4 + 1) * BQ + r] = v.y;
        sm->Qs[(d4 + 2) * BQ + r] = v.z;
        sm->Qs[(d4 + 3) * BQ + r] = v.w;
    }
    if (tid < BQ) { sm->mrow[tid] = -1e30f; sm->lrow[tid] = 0.f; }

    float oacc[4][8];
#pragma unroll
    for (int i = 0; i < 4; i++)
#pragma unroll
        for (int j = 0; j < 8; j++) oacc[i][j] = 0.f;

    const int kb_lo = (qb >= WINDOW / BKB) ? (qb - WINDOW / BKB) : 0;
    const float scl = 0.08838834764831845f;

    for (int kb = kb_lo; kb <= qb; kb++) {
        const int k0 = kb * BKB;

#pragma unroll
        for (int it = 0; it < 8; it++) {
            int f  = tid + it * 256;
            int r  = f >> 5;
            int d4 = (f & 31) << 2;
            float4 v = *(const float4*)(K + (((size_t)(b * SS + k0 + r)) * NKV + kvh) * HD + d4);
            sm->KV[(d4 + 0) * BKB + r] = v.x;
            sm->KV[(d4 + 1) * BKB + r] = v.y;
            sm->KV[(d4 + 2) * BKB + r] = v.z;
            sm->KV[(d4 + 3) * BKB + r] = v.w;
        }
        __syncthreads();

        float sacc[4][4];
#pragma unroll
        for (int i = 0; i < 4; i++)
#pragma unroll
            for (int j = 0; j < 4; j++) sacc[i][j] = 0.f;

#pragma unroll 4
        for (int d = 0; d < HD; d++) {
            float a[4], bb2[4];
            *(float4*)a   = *(const float4*)&sm->Qs[d * BQ  + tq * 4];
            *(float4*)bb2 = *(const float4*)&sm->KV[d * BKB + tx * 4];
#pragma unroll
            for (int i = 0; i < 4; i++)
#pragma unroll
                for (int j = 0; j < 4; j++)
                    sacc[i][j] += a[i] * bb2[j];
        }

#pragma unroll
        for (int i = 0; i < 4; i++) {
            int gi = q0 + tq * 4 + i;
#pragma unroll
            for (int j = 0; j < 4; j++) {
                int gj = k0 + tx * 4 + j;
                int dist = gi - gj;
                float val = (dist >= 0 && dist < WINDOW) ? sacc[i][j] * scl : -1e30f;
                sm->Ss[(tq * 4 + i) * SSTRIDE + tx * 4 + j] = val;
            }
        }
        __syncthreads();

#pragma unroll
        for (int it = 0; it < 8; it++) {
            int f  = tid + it * 256;
            int r  = f >> 5;
            int d4 = (f & 31) << 2;
            float4 v = *(const float4*)(V + (((size_t)(b * SS + k0 + r)) * NKV + kvh) * HD + d4);
            *(float4*)&sm->KV[r * HD + d4] = v;
        }
        {
            float mb = -1e30f;
            const float* row = &sm->Ss[r4 * SSTRIDE + seg * 16];
#pragma unroll
            for (int c = 0; c < 16; c++) mb = fmaxf(mb, row[c]);
            sm->red[r4 * 4 + seg] = mb;
        }
        __syncthreads();

        float mB = fmaxf(fmaxf(sm->red[r4 * 4 + 0], sm->red[r4 * 4 + 1]),
                         fmaxf(sm->red[r4 * 4 + 2], sm->red[r4 * 4 + 3]));
        float mold = sm->mrow[r4];
        float mnew = fmaxf(mold, mB);
        {
            float lsum = 0.f;
            float* row = &sm->Ss[r4 * SSTRIDE + seg * 16];
#pragma unroll
            for (int c = 0; c < 16; c++) {
                float p = __expf(row[c] - mnew);
                row[c] = p;
                lsum += p;
            }
            sm->red2[r4 * 4 + seg] = lsum;
        }
        __syncthreads();

        if (seg == 0) {
            float fac = __expf(mold - mnew);
            sm->frow[r4] = fac;
            sm->mrow[r4] = mnew;
            sm->lrow[r4] = sm->lrow[r4] * fac +
                sm->red2[r4 * 4 + 0] + sm->red2[r4 * 4 + 1] +
                sm->red2[r4 * 4 + 2] + sm->red2[r4 * 4 + 3];
        }
        __syncthreads();

        {
            float fr[4];
#pragma unroll
            for (int i = 0; i < 4; i++) fr[i] = sm->frow[tq * 4 + i];
#pragma unroll
            for (int i = 0; i < 4; i++)
#pragma unroll
                for (int j = 0; j < 8; j++) oacc[i][j] *= fr[i];
        }
#pragma unroll 2
        for (int kk = 0; kk < BKB; kk++) {
            float pv[4];
#pragma unroll
            for (int i = 0; i < 4; i++)
                pv[i] = sm->Ss[(tq * 4 + i) * SSTRIDE + kk];
            float vv[8];
            *(float4*)&vv[0] = *(const float4*)&sm->KV[kk * HD + tx * 8];
            *(float4*)&vv[4] = *(const float4*)&sm->KV[kk * HD + tx * 8 + 4];
#pragma unroll
            for (int i = 0; i < 4; i++)
#pragma unroll
                for (int j = 0; j < 8; j++)
                    oacc[i][j] += pv[i] * vv[j];
        }
        __syncthreads();
    }

    // finalize: divide by l, convert to fp16, write out (16B per thread-row)
#pragma unroll
    for (int i = 0; i < 4; i++) {
        int r = tq * 4 + i;
        float inv = 1.0f / sm->lrow[r];
        __half2 hs[4];
#pragma unroll
        for (int j = 0; j < 4; j++)
            hs[j] = __floats2half2_rn(oacc[i][2*j] * inv, oacc[i][2*j+1] * inv);
        __half* dst = O + (((size_t)(b * SS + q0 + r)) * NH + h) * HD + tx * 8;
        *(uint4*)dst = *(uint4*)hs;
    }
}

// ---------------------------------------------------------------------------
// Launch
// ---------------------------------------------------------------------------
extern "C" void kernel_launch(void* const* d_in, const int* in_sizes, int n_in,
                              void* d_out, int out_size)
{
    const float* x    = (const float*)d_in[0];
    const float* cosT = (const float*)d_in[1];
    const float* sinT = (const float*)d_in[2];
    const float* Wq   = (const float*)d_in[3];
    const float* Wk   = (const float*)d_in[4];
    const float* Wv   = (const float*)d_in[5];
    const float* Wo   = (const float*)d_in[6];
    float* out = (float*)d_out;

    void *pQ, *pK, *pV, *pA, *pXh, *pWq, *pWk, *pWv, *pWo;
    cudaGetSymbolAddress(&pQ, g_Q);
    cudaGetSymbolAddress(&pK, g_K);
    cudaGetSymbolAddress(&pV, g_V);
    cudaGetSymbolAddress(&pA, g_Aoh);
    cudaGetSymbolAddress(&pXh, g_Xh);
    cudaGetSymbolAddress(&pWq, g_Wqh);
    cudaGetSymbolAddress(&pWk, g_Wkh);
    cudaGetSymbolAddress(&pWv, g_Wvh);
    cudaGetSymbolAddress(&pWo, g_Woh);
    float*  Qp = (float*)pQ;    float*  Kp = (float*)pK;
    float*  Vp = (float*)pV;    __half* Ah = (__half*)pA;
    __half* Xh = (__half*)pXh;
    __half* Wqh = (__half*)pWq; __half* Wkh = (__half*)pWk;
    __half* Wvh = (__half*)pWv; __half* Woh = (__half*)pWo;

    // Convert inputs to fp16
    conv_fp16_kernel<<<(MROWS * EE / 4) / 256, 256>>>(x, Xh);
    conv_fp16_kernel<<<(NH * HD * EE / 4) / 256, 256>>>(Wq, Wqh);
    conv_fp16_kernel<<<(NKV * HD * EE / 4) / 256, 256>>>(Wk, Wkh);
    conv_fp16_kernel<<<(NKV * HD * EE / 4) / 256, 256>>>(Wv, Wvh);
    conv_fp16_kernel<<<(EE * EE / 4) / 256, 256>>>(Wo, Woh);

    // Projections (fp16 mma.sync, fp32 out)
    cudaFuncSetAttribute(gemm_fp16, cudaFuncAttributeMaxDynamicSharedMemorySize, GEMM_DYN);
    gemm_fp16<<<dim3(MROWS / TM, (NH  * HD) / TN), 256, GEMM_DYN>>>(Xh, Wqh, Qp, NH  * HD, EE);
    gemm_fp16<<<dim3(MROWS / TM, (NKV * HD) / TN), 256, GEMM_DYN>>>(Xh, Wkh, Kp, NKV * HD, EE);
    gemm_fp16<<<dim3(MROWS / TM, (NKV * HD) / TN), 256, GEMM_DYN>>>(Xh, Wvh, Vp, NKV * HD, EE);

    // RoPE (fp32)
    rope_kernel<<<(MROWS * NH  * 64) / 256, 256>>>(Qp, cosT, sinT, NH);
    rope_kernel<<<(MROWS * NKV * 64) / 256, 256>>>(Kp, cosT, sinT, NKV);

    // Attention (fp32 math, fp16 output)
    int smem = (int)sizeof(AttnSmem);
    cudaFuncSetAttribute(attn_kernel, cudaFuncAttributeMaxDynamicSharedMemorySize, smem);
    attn_kernel<<<dim3(SS / BQ, NH, BB), 256, smem>>>(Qp, Kp, Vp, Ah);

    // Output projection (fp16 in, fp32 out)
    gemm_fp16<<<dim3(MROWS / TM, EE / TN), 256, GEMM_DYN>>>(Ah, Woh, out, EE, EE);
}

// round 11
// speedup vs baseline: 5.1339x; 2.3804x over previous
#include <cuda_runtime.h>
#include <cuda_fp16.h>
#include <cstdint>

#define BB 2
#define SS 2048
#define EE 2048
#define NH 16
#define NKV 4
#define HD 128
#define WINDOW 1024
#define MROWS (BB*SS)   // 4096

// ---------------- scratch (device globals) ----------------
__device__ float  g_Q [MROWS * NH  * HD];    // fp32 Q (pre-rope)
__device__ float  g_K [MROWS * NKV * HD];    // fp32 K (pre-rope)
__device__ __half g_Qh[MROWS * NH  * HD];    // fp16 Q (post-rope)
__device__ __half g_Kh[MROWS * NKV * HD];    // fp16 K (post-rope)
__device__ __half g_Vh[MROWS * NKV * HD];    // fp16 V
__device__ __half g_Aoh[MROWS * NH  * HD];   // attention out, fp16
__device__ __half g_Xh [MROWS * EE];
__device__ __half g_Wqh[NH  * HD * EE];
__device__ __half g_Wkh[NKV * HD * EE];
__device__ __half g_Wvh[NKV * HD * EE];
__device__ __half g_Woh[EE * EE];

// ---------------- helpers ----------------
__device__ __forceinline__ uint32_t smem_u32(const void* p) {
    uint32_t a;
    asm("{ .reg .u64 t; cvta.to.shared.u64 t, %1; cvt.u32.u64 %0, t; }" : "=r"(a) : "l"(p));
    return a;
}
__device__ __forceinline__ void cp16(uint32_t dst, const void* src) {
    asm volatile("cp.async.cg.shared.global [%0], [%1], 16;" :: "r"(dst), "l"(src) : "memory");
}
__device__ __forceinline__ uint32_t swz(uint32_t off) {   // SW128 (Swizzle<3,4,3>)
    return off ^ ((off >> 3) & 0x70);
}
__device__ __forceinline__ void ldsm4(uint32_t& r0, uint32_t& r1, uint32_t& r2,
                                      uint32_t& r3, uint32_t addr) {
    asm volatile("ldmatrix.sync.aligned.m8n8.x4.shared.b16 {%0,%1,%2,%3}, [%4];"
                 : "=r"(r0), "=r"(r1), "=r"(r2), "=r"(r3) : "r"(addr));
}
__device__ __forceinline__ void ldsm4t(uint32_t& r0, uint32_t& r1, uint32_t& r2,
                                       uint32_t& r3, uint32_t addr) {
    asm volatile("ldmatrix.sync.aligned.m8n8.x4.trans.shared.b16 {%0,%1,%2,%3}, [%4];"
                 : "=r"(r0), "=r"(r1), "=r"(r2), "=r"(r3) : "r"(addr));
}
__device__ __forceinline__ void mma_fp16(float& c0, float& c1, float& c2, float& c3,
                                         uint32_t a0, uint32_t a1, uint32_t a2, uint32_t a3,
                                         uint32_t b0, uint32_t b1) {
    asm volatile("mma.sync.aligned.m16n8k16.row.col.f32.f16.f16.f32 "
                 "{%0,%1,%2,%3}, {%4,%5,%6,%7}, {%8,%9}, {%0,%1,%2,%3};"
                 : "+f"(c0), "+f"(c1), "+f"(c2), "+f"(c3)
                 : "r"(a0), "r"(a1), "r"(a2), "r"(a3), "r"(b0), "r"(b1));
}
__device__ __forceinline__ uint32_t packh2(float a, float b) {
    __half2 h = __floats2half2_rn(a, b);
    return *(uint32_t*)&h;
}

// ---------------------------------------------------------------------------
// fp32 -> fp16
// ---------------------------------------------------------------------------
__global__ __launch_bounds__(256) void conv_fp16_kernel(const float* __restrict__ in,
                                                        __half* __restrict__ out) {
    int i = blockIdx.x * blockDim.x + threadIdx.x;
    float4 v = ((const float4*)in)[i];
    ((__half2*)out)[i * 2]     = __floats2half2_rn(v.x, v.y);
    ((__half2*)out)[i * 2 + 1] = __floats2half2_rn(v.z, v.w);
}

// ---------------------------------------------------------------------------
// FP16 mma.sync GEMM (templated fp32/fp16 output). C = A[M,K] * B[N,K]^T.
// ---------------------------------------------------------------------------
#define TM 128
#define TN 128
#define KC 64
#define NSTAGE 3
#define A_BYTES (TM*KC*2)
#define STAGE_BYTES (A_BYTES*2)
#define GEMM_DYN (NSTAGE*STAGE_BYTES + 1024)

__device__ __forceinline__ void gemm_load_chunk(
    uint32_t stageBase, const __half* __restrict__ A, const __half* __restrict__ B,
    int m0, int n0, int k0, int K, int tid)
{
#pragma unroll
    for (int i = 0; i < 8; i++) {
        int id = tid + i * 256;
        int row = (id >> 3) & 127;
        int c16 = id & 7;
        uint32_t off = (uint32_t)(row * 128 + c16 * 16);
        if (id < 1024) {
            cp16(stageBase + swz(off), A + (size_t)(m0 + row) * K + k0 + c16 * 8);
        } else {
            cp16(stageBase + A_BYTES + swz(off), B + (size_t)(n0 + row) * K + k0 + c16 * 8);
        }
    }
}

template<bool HOUT>
__global__ __launch_bounds__(256, 2) void gemm_fp16(
    const __half* __restrict__ A, const __half* __restrict__ B,
    void* __restrict__ Cv, int N, int K)
{
    extern __shared__ char dynsmem[];
    uint32_t base = (smem_u32(dynsmem) + 1023) & ~1023u;

    const int tid  = threadIdx.x;
    const int wid  = tid >> 5;
    const int lane = tid & 31;
    const int wm   = wid & 1;
    const int wn   = wid >> 1;
    const int grp  = lane >> 2;
    const int tig  = lane & 3;
    const int t8    = lane & 7;
    const int which = lane >> 3;
    const int m0 = blockIdx.x * TM;
    const int n0 = blockIdx.y * TN;
    const int NC = K / KC;

    float acc[4][4][4];
#pragma unroll
    for (int a = 0; a < 4; a++)
#pragma unroll
        for (int b = 0; b < 4; b++)
#pragma unroll
            for (int c = 0; c < 4; c++) acc[a][b][c] = 0.f;

    uint32_t aRowOff[4], bRowOff[2];
#pragma unroll
    for (int mt = 0; mt < 4; mt++)
        aRowOff[mt] = (uint32_t)((wm * 64 + mt * 16 + (which & 1) * 8 + t8) * 128 + (which >> 1) * 16);
#pragma unroll
    for (int p = 0; p < 2; p++)
        bRowOff[p] = (uint32_t)((wn * 32 + p * 16 + (which >> 1) * 8 + t8) * 128 + (which & 1) * 16);

#pragma unroll
    for (int pc = 0; pc < NSTAGE - 1; pc++) {
        gemm_load_chunk(base + pc * STAGE_BYTES, A, B, m0, n0, pc * KC, K, tid);
        asm volatile("cp.async.commit_group;" ::: "memory");
    }

    for (int c = 0; c < NC; c++) {
        asm volatile("cp.async.wait_group %0;" :: "n"(NSTAGE - 2) : "memory");
        __syncthreads();

        int lc = c + NSTAGE - 1;
        if (lc < NC)
            gemm_load_chunk(base + (lc % NSTAGE) * STAGE_BYTES, A, B, m0, n0, lc * KC, K, tid);
        asm volatile("cp.async.commit_group;" ::: "memory");

        uint32_t aB = base + (c % NSTAGE) * STAGE_BYTES;
        uint32_t bB = aB + A_BYTES;

#pragma unroll
        for (int ks = 0; ks < 4; ks++) {
            uint32_t kbyte = (uint32_t)(ks * 32);
            uint32_t af[4][4], bf[2][4];
#pragma unroll
            for (int mt = 0; mt < 4; mt++)
                ldsm4(af[mt][0], af[mt][1], af[mt][2], af[mt][3], aB + swz(aRowOff[mt] + kbyte));
#pragma unroll
            for (int p = 0; p < 2; p++)
                ldsm4(bf[p][0], bf[p][1], bf[p][2], bf[p][3], bB + swz(bRowOff[p] + kbyte));
#pragma unroll
            for (int mt = 0; mt < 4; mt++) {
#pragma unroll
                for (int p = 0; p < 2; p++) {
                    mma_fp16(acc[mt][2*p][0], acc[mt][2*p][1], acc[mt][2*p][2], acc[mt][2*p][3],
                             af[mt][0], af[mt][1], af[mt][2], af[mt][3], bf[p][0], bf[p][1]);
                    mma_fp16(acc[mt][2*p+1][0], acc[mt][2*p+1][1], acc[mt][2*p+1][2], acc[mt][2*p+1][3],
                             af[mt][0], af[mt][1], af[mt][2], af[mt][3], bf[p][2], bf[p][3]);
                }
            }
        }
    }

#pragma unroll
    for (int mt = 0; mt < 4; mt++) {
        int rbase = m0 + wm * 64 + mt * 16 + grp;
#pragma unroll
        for (int nt = 0; nt < 4; nt++) {
            int col = n0 + wn * 32 + nt * 8 + 2 * tig;
            if (HOUT) {
                __half* C = (__half*)Cv;
                *(__half2*)(C + (size_t)rbase * N + col)       = __floats2half2_rn(acc[mt][nt][0], acc[mt][nt][1]);
                *(__half2*)(C + (size_t)(rbase + 8) * N + col) = __floats2half2_rn(acc[mt][nt][2], acc[mt][nt][3]);
            } else {
                float* C = (float*)Cv;
                float* d0 = C + (size_t)rbase * N + col;
                float* d1 = C + (size_t)(rbase + 8) * N + col;
                d0[0] = acc[mt][nt][0]; d0[1] = acc[mt][nt][1];
                d1[0] = acc[mt][nt][2]; d1[1] = acc[mt][nt][3];
            }
        }
    }
}

// ---------------------------------------------------------------------------
// RoPE fp32 -> fp16
// ---------------------------------------------------------------------------
__global__ __launch_bounds__(256) void rope_h_kernel(
    const float* __restrict__ X, __half* __restrict__ Xh,
    const float* __restrict__ cosT, const float* __restrict__ sinT, int nh)
{
    int idx = blockIdx.x * blockDim.x + threadIdx.x;
    int d   = idx & 63;
    int t   = idx >> 6;
    int h   = t % nh;
    int bs  = t / nh;
    int s   = bs & (SS - 1);

    float c  = cosT[s * HD + d];
    float sn = sinT[s * HD + d];
    size_t base = ((size_t)bs * nh + h) * HD;
    float x1 = X[base + d];
    float x2 = X[base + d + 64];
    Xh[base + d]      = __float2half(x1 * c - x2 * sn);
    Xh[base + d + 64] = __float2half(x2 * c + x1 * sn);
}

// ---------------------------------------------------------------------------
// FP16 tensor-core flash attention, sliding window, GQA.
// CTA: 64 q-rows x (h,b). 8 warps: wr=w&3 row-tile(16), wc=w>>2 k-slice(32).
// HD split in two 64-wide chunks -> all smem rows are 128B (SW128 + ldsm).
// S accs convert in-register to PV A-fragments. V via ldmatrix.trans.
// ---------------------------------------------------------------------------
#define AT_QBYTES 16384                 // 2 chunks x 64 x 128B
#define AT_KVBUF  32768                 // Ks[2 chunks] + Vs[2 chunks]
#define AT_OFF_KV AT_QBYTES
#define AT_OFF_RED  (AT_OFF_KV + 2*AT_KVBUF)          // 81920
#define AT_OFF_RED2 (AT_OFF_RED + 64*2*4)
#define AT_SMEM     (AT_OFF_RED2 + 64*2*4)            // 82944
#define OB_STRIDE 132

__device__ __forceinline__ void at_load_q(uint32_t qBase, const __half* __restrict__ Qg,
                                          int b, int q0, int h, int tid) {
#pragma unroll
    for (int i = 0; i < 4; i++) {
        int id = tid + i * 256;          // 1024 16B units
        int row = id >> 4, u = id & 15;
        int ch = u >> 3, c16 = u & 7;
        const __half* src = Qg + ((size_t)(b * SS + q0 + row) * NH + h) * HD + ch * 64 + c16 * 8;
        cp16(qBase + ch * 8192 + swz((uint32_t)(row * 128 + c16 * 16)), src);
    }
}
__device__ __forceinline__ void at_load_kv(uint32_t kvBase, const __half* __restrict__ Kg,
                                           const __half* __restrict__ Vg,
                                           int b, int k0, int kvh, int tid) {
#pragma unroll
    for (int i = 0; i < 8; i++) {
        int id = tid + i * 256;          // 2048 units: 1024 K + 1024 V
        int isV = id >= 1024;
        int cid = id & 1023;
        int row = cid >> 4, u = cid & 15;
        int ch = u >> 3, c16 = u & 7;
        const __half* src = (isV ? Vg : Kg) +
            ((size_t)(b * SS + k0 + row) * NKV + kvh) * HD + ch * 64 + c16 * 8;
        cp16(kvBase + (isV ? 16384 : 0) + ch * 8192 + swz((uint32_t)(row * 128 + c16 * 16)), src);
    }
}

__global__ __launch_bounds__(256) void attn_mma_kernel(
    const __half* __restrict__ Q, const __half* __restrict__ K,
    const __half* __restrict__ V, __half* __restrict__ O)
{
    extern __shared__ char smc[];
    const uint32_t sb = smem_u32(smc);
    float* red  = (float*)(smc + AT_OFF_RED);
    float* red2 = (float*)(smc + AT_OFF_RED2);

    const int tid = threadIdx.x;
    const int w = tid >> 5, lane = tid & 31;
    const int grp = lane >> 2, tl = lane & 3;
    const int t8 = lane & 7, which = lane >> 3;
    const int wr = w & 3, wc = w >> 2;
    const int qb = blockIdx.x, h = blockIdx.y, b = blockIdx.z;
    const int kvh = h >> 2;
    const int q0 = qb * 64;
    const int grow = wr * 16 + grp;         // block-local row (and grow+8)
    const float scl = 0.08838834764831845f;

    // ldsm offsets (in-chunk byte offsets before swz)
    const uint32_t qoff = (uint32_t)((wr * 16 + (which & 1) * 8 + t8) * 128 + (which >> 1) * 16);
    uint32_t koff[2], voff[2];
#pragma unroll
    for (int p = 0; p < 2; p++)
        koff[p] = (uint32_t)((wc * 32 + p * 16 + (which >> 1) * 8 + t8) * 128 + (which & 1) * 16);
#pragma unroll
    for (int ks = 0; ks < 2; ks++)
        voff[ks] = (uint32_t)((wc * 32 + ks * 16 + (which & 1) * 8 + t8) * 128 + (which >> 1) * 16);

    float m1 = -1e30f, m2 = -1e30f, l1 = 0.f, l2 = 0.f;
    float oacc[16][4];
#pragma unroll
    for (int t = 0; t < 16; t++)
#pragma unroll
        for (int e = 0; e < 4; e++) oacc[t][e] = 0.f;

    const int kb_lo = (qb >= 16) ? (qb - 16) : 0;

    // prologue
    at_load_q(sb, Q, b, q0, h, tid);
    at_load_kv(sb + AT_OFF_KV, K, V, b, kb_lo * 64, kvh, tid);
    asm volatile("cp.async.commit_group;" ::: "memory");

    for (int kb = kb_lo; kb <= qb; kb++) {
        const int cur = (kb - kb_lo) & 1;
        const int k0 = kb * 64;
        const uint32_t kvB = sb + AT_OFF_KV + cur * AT_KVBUF;

        __syncthreads();   // all threads done with buf cur^1 (prev compute)
        if (kb < qb) {
            at_load_kv(sb + AT_OFF_KV + (cur ^ 1) * AT_KVBUF, K, V, b, k0 + 64, kvh, tid);
            asm volatile("cp.async.commit_group;" ::: "memory");
            asm volatile("cp.async.wait_group 1;" ::: "memory");
        } else {
            asm volatile("cp.async.wait_group 0;" ::: "memory");
        }
        __syncthreads();   // buf cur visible

        // ---- S = Q K^T (warp tile 16 x 32) ----
        float sacc[4][4];
#pragma unroll
        for (int nt = 0; nt < 4; nt++)
#pragma unroll
            for (int e = 0; e < 4; e++) sacc[nt][e] = 0.f;

#pragma unroll
        for (int c = 0; c < 2; c++) {
            uint32_t qB = sb + c * 8192;
            uint32_t kB = kvB + c * 8192;
#pragma unroll
            for (int ks = 0; ks < 4; ks++) {
                uint32_t kbyte = (uint32_t)(ks * 32);
                uint32_t af[4], bf[2][4];
                ldsm4(af[0], af[1], af[2], af[3], qB + swz(qoff + kbyte));
#pragma unroll
                for (int p = 0; p < 2; p++)
                    ldsm4(bf[p][0], bf[p][1], bf[p][2], bf[p][3], kB + swz(koff[p] + kbyte));
#pragma unroll
                for (int p = 0; p < 2; p++) {
                    mma_fp16(sacc[2*p][0], sacc[2*p][1], sacc[2*p][2], sacc[2*p][3],
                             af[0], af[1], af[2], af[3], bf[p][0], bf[p][1]);
                    mma_fp16(sacc[2*p+1][0], sacc[2*p+1][1], sacc[2*p+1][2], sacc[2*p+1][3],
                             af[0], af[1], af[2], af[3], bf[p][2], bf[p][3]);
                }
            }
        }

        // scale + mask (only diagonal / far-edge blocks need masking)
#pragma unroll
        for (int nt = 0; nt < 4; nt++)
#pragma unroll
            for (int e = 0; e < 4; e++) sacc[nt][e] *= scl;

        if (kb == qb || qb - kb == 16) {
            int r0g = q0 + grow;
#pragma unroll
            for (int nt = 0; nt < 4; nt++) {
                int cbase = k0 + wc * 32 + nt * 8 + 2 * tl;
#pragma unroll
                for (int e = 0; e < 4; e++) {
                    int gi = r0g + (e >> 1) * 8;
                    int gj = cbase + (e & 1);
                    int dist = gi - gj;
                    if (!(dist >= 0 && dist < WINDOW)) sacc[nt][e] = -1e30f;
                }
            }
        }

        // ---- online softmax ----
        float mx1 = -1e30f, mx2 = -1e30f;
#pragma unroll
        for (int nt = 0; nt < 4; nt++) {
            mx1 = fmaxf(mx1, fmaxf(sacc[nt][0], sacc[nt][1]));
            mx2 = fmaxf(mx2, fmaxf(sacc[nt][2], sacc[nt][3]));
        }
        mx1 = fmaxf(mx1, __shfl_xor_sync(0xffffffffu, mx1, 1));
        mx1 = fmaxf(mx1, __shfl_xor_sync(0xffffffffu, mx1, 2));
        mx2 = fmaxf(mx2, __shfl_xor_sync(0xffffffffu, mx2, 1));
        mx2 = fmaxf(mx2, __shfl_xor_sync(0xffffffffu, mx2, 2));
        if (tl == 0) {
            red[grow * 2 + wc]       = mx1;
            red[(grow + 8) * 2 + wc] = mx2;
        }
        __syncthreads();

        float mn1 = fmaxf(m1, fmaxf(red[grow * 2], red[grow * 2 + 1]));
        float mn2 = fmaxf(m2, fmaxf(red[(grow + 8) * 2], red[(grow + 8) * 2 + 1]));
        float f1 = __expf(m1 - mn1);
        float f2 = __expf(m2 - mn2);
        m1 = mn1; m2 = mn2;

        float s1 = 0.f, s2 = 0.f;
        uint32_t ph[4][2];
#pragma unroll
        for (int nt = 0; nt < 4; nt++) {
            float p0 = __expf(sacc[nt][0] - mn1);
            float p1 = __expf(sacc[nt][1] - mn1);
            float p2 = __expf(sacc[nt][2] - mn2);
            float p3 = __expf(sacc[nt][3] - mn2);
            s1 += p0 + p1; s2 += p2 + p3;
            ph[nt][0] = packh2(p0, p1);
            ph[nt][1] = packh2(p2, p3);
        }
        s1 += __shfl_xor_sync(0xffffffffu, s1, 1);
        s1 += __shfl_xor_sync(0xffffffffu, s1, 2);
        s2 += __shfl_xor_sync(0xffffffffu, s2, 1);
        s2 += __shfl_xor_sync(0xffffffffu, s2, 2);
        if (tl == 0) {
            red2[grow * 2 + wc]       = s1;
            red2[(grow + 8) * 2 + wc] = s2;
        }
        // rescale O while the sum lands
#pragma unroll
        for (int t = 0; t < 16; t++) {
            oacc[t][0] *= f1; oacc[t][1] *= f1;
            oacc[t][2] *= f2; oacc[t][3] *= f2;
        }
        __syncthreads();
        l1 = l1 * f1 + red2[grow * 2] + red2[grow * 2 + 1];
        l2 = l2 * f2 + red2[(grow + 8) * 2] + red2[(grow + 8) * 2 + 1];

        // ---- O += P V  (A-frags from ph in-register; B via ldsm.trans) ----
#pragma unroll
        for (int c = 0; c < 2; c++) {
            uint32_t vB = kvB + 16384 + c * 8192;
#pragma unroll
            for (int db = 0; db < 4; db++) {
#pragma unroll
                for (int ks = 0; ks < 2; ks++) {
                    uint32_t bf0, bf1, bf2, bf3;
                    ldsm4t(bf0, bf1, bf2, bf3, vB + swz(voff[ks] + (uint32_t)(db * 32)));
                    int tlo = (c * 4 + db) * 2, thi = tlo + 1;
                    mma_fp16(oacc[tlo][0], oacc[tlo][1], oacc[tlo][2], oacc[tlo][3],
                             ph[2*ks][0], ph[2*ks][1], ph[2*ks+1][0], ph[2*ks+1][1],
                             bf0, bf1);
                    mma_fp16(oacc[thi][0], oacc[thi][1], oacc[thi][2], oacc[thi][3],
                             ph[2*ks][0], ph[2*ks][1], ph[2*ks+1][0], ph[2*ks+1][1],
                             bf2, bf3);
                }
            }
        }
    }

    // ---- combine warp pairs (wc 0/1) and write out ----
    __syncthreads();
    float* Obuf = (float*)(smc + AT_OFF_KV);    // 64 x OB_STRIDE floats (overlays KV)
    if (wc == 0) {
#pragma unroll
        for (int t = 0; t < 16; t++) {
            int d = (t >> 3) * 64 + ((t >> 1) & 3) * 16 + (t & 1) * 8 + 2 * tl;
            *(float2*)&Obuf[grow * OB_STRIDE + d]       = make_float2(oacc[t][0], oacc[t][1]);
            *(float2*)&Obuf[(grow + 8) * OB_STRIDE + d] = make_float2(oacc[t][2], oacc[t][3]);
        }
    }
    __syncthreads();
    if (wc == 1) {
        float inv1 = 1.0f / l1;
        float inv2 = 1.0f / l2;
        __half* dst1 = O + ((size_t)(b * SS + q0 + grow) * NH + h) * HD;
        __half* dst2 = O + ((size_t)(b * SS + q0 + grow + 8) * NH + h) * HD;
#pragma unroll
        for (int t = 0; t < 16; t++) {
            int d = (t >> 3) * 64 + ((t >> 1) & 3) * 16 + (t & 1) * 8 + 2 * tl;
            float2 p1 = *(float2*)&Obuf[grow * OB_STRIDE + d];
            float2 p2 = *(float2*)&Obuf[(grow + 8) * OB_STRIDE + d];
            *(__half2*)(dst1 + d) = __floats2half2_rn((p1.x + oacc[t][0]) * inv1,
                                                      (p1.y + oacc[t][1]) * inv1);
            *(__half2*)(dst2 + d) = __floats2half2_rn((p2.x + oacc[t][2]) * inv2,
                                                      (p2.y + oacc[t][3]) * inv2);
        }
    }
}

// ---------------------------------------------------------------------------
// Launch
// ---------------------------------------------------------------------------
extern "C" void kernel_launch(void* const* d_in, const int* in_sizes, int n_in,
                              void* d_out, int out_size)
{
    const float* x    = (const float*)d_in[0];
    const float* cosT = (const float*)d_in[1];
    const float* sinT = (const float*)d_in[2];
    const float* Wq   = (const float*)d_in[3];
    const float* Wk   = (const float*)d_in[4];
    const float* Wv   = (const float*)d_in[5];
    const float* Wo   = (const float*)d_in[6];
    float* out = (float*)d_out;

    void *pQ, *pK, *pQh, *pKh, *pVh, *pA, *pXh, *pWq, *pWk, *pWv, *pWo;
    cudaGetSymbolAddress(&pQ, g_Q);
    cudaGetSymbolAddress(&pK, g_K);
    cudaGetSymbolAddress(&pQh, g_Qh);
    cudaGetSymbolAddress(&pKh, g_Kh);
    cudaGetSymbolAddress(&pVh, g_Vh);
    cudaGetSymbolAddress(&pA, g_Aoh);
    cudaGetSymbolAddress(&pXh, g_Xh);
    cudaGetSymbolAddress(&pWq, g_Wqh);
    cudaGetSymbolAddress(&pWk, g_Wkh);
    cudaGetSymbolAddress(&pWv, g_Wvh);
    cudaGetSymbolAddress(&pWo, g_Woh);
    float*  Qp = (float*)pQ;    float*  Kp = (float*)pK;
    __half* Qh = (__half*)pQh;  __half* Kh = (__half*)pKh;
    __half* Vh = (__half*)pVh;  __half* Ah = (__half*)pA;
    __half* Xh = (__half*)pXh;
    __half* Wqh = (__half*)pWq; __half* Wkh = (__half*)pWk;
    __half* Wvh = (__half*)pWv; __half* Woh = (__half*)pWo;

    // Convert inputs to fp16
    conv_fp16_kernel<<<(MROWS * EE / 4) / 256, 256>>>(x, Xh);
    conv_fp16_kernel<<<(NH * HD * EE / 4) / 256, 256>>>(Wq, Wqh);
    conv_fp16_kernel<<<(NKV * HD * EE / 4) / 256, 256>>>(Wk, Wkh);
    conv_fp16_kernel<<<(NKV * HD * EE / 4) / 256, 256>>>(Wv, Wvh);
    conv_fp16_kernel<<<(EE * EE / 4) / 256, 256>>>(Wo, Woh);

    // Projections
    cudaFuncSetAttribute(gemm_fp16<false>, cudaFuncAttributeMaxDynamicSharedMemorySize, GEMM_DYN);
    cudaFuncSetAttribute(gemm_fp16<true>,  cudaFuncAttributeMaxDynamicSharedMemorySize, GEMM_DYN);
    gemm_fp16<false><<<dim3(MROWS / TM, (NH  * HD) / TN), 256, GEMM_DYN>>>(Xh, Wqh, Qp, NH  * HD, EE);
    gemm_fp16<false><<<dim3(MROWS / TM, (NKV * HD) / TN), 256, GEMM_DYN>>>(Xh, Wkh, Kp, NKV * HD, EE);
    gemm_fp16<true ><<<dim3(MROWS / TM, (NKV * HD) / TN), 256, GEMM_DYN>>>(Xh, Wvh, Vh, NKV * HD, EE);

    // RoPE (fp32 in -> fp16 out)
    rope_h_kernel<<<(MROWS * NH  * 64) / 256, 256>>>(Qp, Qh, cosT, sinT, NH);
    rope_h_kernel<<<(MROWS * NKV * 64) / 256, 256>>>(Kp, Kh, cosT, sinT, NKV);

    // Attention (fp16 tensor cores)
    cudaFuncSetAttribute(attn_mma_kernel, cudaFuncAttributeMaxDynamicSharedMemorySize, AT_SMEM);
    attn_mma_kernel<<<dim3(SS / 64, NH, BB), 256, AT_SMEM>>>(Qh, Kh, Vh, Ah);

    // Output projection
    gemm_fp16<false><<<dim3(MROWS / TM, EE / TN), 256, GEMM_DYN>>>(Ah, Woh, out, EE, EE);
}

// round 12
// speedup vs baseline: 7.4480x; 1.4507x over previous
#include <cuda_runtime.h>
#include <cuda_fp16.h>
#include <cstdint>

#define BB 2
#define SS 2048
#define EE 2048
#define NH 16
#define NKV 4
#define HD 128
#define WINDOW 1024
#define MROWS (BB*SS)   // 4096

// ---------------- scratch (device globals) ----------------
__device__ __half g_Qh[MROWS * NH  * HD];    // fp16 Q (post-rope)
__device__ __half g_Kh[MROWS * NKV * HD];    // fp16 K (post-rope)
__device__ __half g_Vh[MROWS * NKV * HD];    // fp16 V
__device__ __half g_Aoh[MROWS * NH  * HD];   // attention out, fp16
__device__ __half g_Xh [MROWS * EE];
__device__ __half g_Wqh[NH  * HD * EE];
__device__ __half g_Wkh[NKV * HD * EE];
__device__ __half g_Wvh[NKV * HD * EE];
__device__ __half g_Woh[EE * EE];

// ---------------- helpers ----------------
__device__ __forceinline__ uint32_t smem_u32(const void* p) {
    uint32_t a;
    asm("{ .reg .u64 t; cvta.to.shared.u64 t, %1; cvt.u32.u64 %0, t; }" : "=r"(a) : "l"(p));
    return a;
}
__device__ __forceinline__ void cp16(uint32_t dst, const void* src) {
    asm volatile("cp.async.cg.shared.global [%0], [%1], 16;" :: "r"(dst), "l"(src) : "memory");
}
__device__ __forceinline__ uint32_t swz(uint32_t off) {   // SW128 (Swizzle<3,4,3>)
    return off ^ ((off >> 3) & 0x70);
}
__device__ __forceinline__ void ldsm4(uint32_t& r0, uint32_t& r1, uint32_t& r2,
                                      uint32_t& r3, uint32_t addr) {
    asm volatile("ldmatrix.sync.aligned.m8n8.x4.shared.b16 {%0,%1,%2,%3}, [%4];"
                 : "=r"(r0), "=r"(r1), "=r"(r2), "=r"(r3) : "r"(addr));
}
__device__ __forceinline__ void ldsm4t(uint32_t& r0, uint32_t& r1, uint32_t& r2,
                                       uint32_t& r3, uint32_t addr) {
    asm volatile("ldmatrix.sync.aligned.m8n8.x4.trans.shared.b16 {%0,%1,%2,%3}, [%4];"
                 : "=r"(r0), "=r"(r1), "=r"(r2), "=r"(r3) : "r"(addr));
}
__device__ __forceinline__ void mma_fp16(float& c0, float& c1, float& c2, float& c3,
                                         uint32_t a0, uint32_t a1, uint32_t a2, uint32_t a3,
                                         uint32_t b0, uint32_t b1) {
    asm volatile("mma.sync.aligned.m16n8k16.row.col.f32.f16.f16.f32 "
                 "{%0,%1,%2,%3}, {%4,%5,%6,%7}, {%8,%9}, {%0,%1,%2,%3};"
                 : "+f"(c0), "+f"(c1), "+f"(c2), "+f"(c3)
                 : "r"(a0), "r"(a1), "r"(a2), "r"(a3), "r"(b0), "r"(b1));
}
__device__ __forceinline__ uint32_t packh2(float a, float b) {
    __half2 h = __floats2half2_rn(a, b);
    return *(uint32_t*)&h;
}

// ---------------------------------------------------------------------------
// fp32 -> fp16
// ---------------------------------------------------------------------------
__global__ __launch_bounds__(256) void conv_fp16_kernel(const float* __restrict__ in,
                                                        __half* __restrict__ out) {
    int i = blockIdx.x * blockDim.x + threadIdx.x;
    float4 v = ((const float4*)in)[i];
    ((__half2*)out)[i * 2]     = __floats2half2_rn(v.x, v.y);
    ((__half2*)out)[i * 2 + 1] = __floats2half2_rn(v.z, v.w);
}

// ---------------------------------------------------------------------------
// FP16 mma.sync GEMM.  C = A[M,K] * B[N,K]^T.
// OMODE: 0 = fp32 out, 1 = fp16 out, 2 = RoPE + fp16 out (tile = one head).
// ---------------------------------------------------------------------------
#define TM 128
#define TN 128
#define KC 64
#define NSTAGE 3
#define A_BYTES (TM*KC*2)
#define STAGE_BYTES (A_BYTES*2)
#define GEMM_DYN (NSTAGE*STAGE_BYTES + 1024)   // 99328 (>= 128*132*4 rope stage)

__device__ __forceinline__ void gemm_load_chunk(
    uint32_t stageBase, const __half* __restrict__ A, const __half* __restrict__ B,
    int m0, int n0, int k0, int K, int tid)
{
#pragma unroll
    for (int i = 0; i < 8; i++) {
        int id = tid + i * 256;
        int row = (id >> 3) & 127;
        int c16 = id & 7;
        uint32_t off = (uint32_t)(row * 128 + c16 * 16);
        if (id < 1024) {
            cp16(stageBase + swz(off), A + (size_t)(m0 + row) * K + k0 + c16 * 8);
        } else {
            cp16(stageBase + A_BYTES + swz(off), B + (size_t)(n0 + row) * K + k0 + c16 * 8);
        }
    }
}

template<int OMODE>
__global__ __launch_bounds__(256, 2) void gemm_fp16(
    const __half* __restrict__ A, const __half* __restrict__ B,
    void* __restrict__ Cv, int N, int K,
    const float* __restrict__ cosT, const float* __restrict__ sinT, int nheads)
{
    extern __shared__ char dynsmem[];
    uint32_t base = (smem_u32(dynsmem) + 1023) & ~1023u;

    const int tid  = threadIdx.x;
    const int wid  = tid >> 5;
    const int lane = tid & 31;
    const int wm   = wid & 1;
    const int wn   = wid >> 1;
    const int grp  = lane >> 2;
    const int tig  = lane & 3;
    const int t8    = lane & 7;
    const int which = lane >> 3;
    const int m0 = blockIdx.x * TM;
    const int n0 = blockIdx.y * TN;
    const int NC = K / KC;

    float acc[4][4][4];
#pragma unroll
    for (int a = 0; a < 4; a++)
#pragma unroll
        for (int b = 0; b < 4; b++)
#pragma unroll
            for (int c = 0; c < 4; c++) acc[a][b][c] = 0.f;

    uint32_t aRowOff[4], bRowOff[2];
#pragma unroll
    for (int mt = 0; mt < 4; mt++)
        aRowOff[mt] = (uint32_t)((wm * 64 + mt * 16 + (which & 1) * 8 + t8) * 128 + (which >> 1) * 16);
#pragma unroll
    for (int p = 0; p < 2; p++)
        bRowOff[p] = (uint32_t)((wn * 32 + p * 16 + (which >> 1) * 8 + t8) * 128 + (which & 1) * 16);

#pragma unroll
    for (int pc = 0; pc < NSTAGE - 1; pc++) {
        gemm_load_chunk(base + pc * STAGE_BYTES, A, B, m0, n0, pc * KC, K, tid);
        asm volatile("cp.async.commit_group;" ::: "memory");
    }

    for (int c = 0; c < NC; c++) {
        asm volatile("cp.async.wait_group %0;" :: "n"(NSTAGE - 2) : "memory");
        __syncthreads();

        int lc = c + NSTAGE - 1;
        if (lc < NC)
            gemm_load_chunk(base + (lc % NSTAGE) * STAGE_BYTES, A, B, m0, n0, lc * KC, K, tid);
        asm volatile("cp.async.commit_group;" ::: "memory");

        uint32_t aB = base + (c % NSTAGE) * STAGE_BYTES;
        uint32_t bB = aB + A_BYTES;

#pragma unroll
        for (int ks = 0; ks < 4; ks++) {
            uint32_t kbyte = (uint32_t)(ks * 32);
            uint32_t af[4][4], bf[2][4];
#pragma unroll
            for (int mt = 0; mt < 4; mt++)
                ldsm4(af[mt][0], af[mt][1], af[mt][2], af[mt][3], aB + swz(aRowOff[mt] + kbyte));
#pragma unroll
            for (int p = 0; p < 2; p++)
                ldsm4(bf[p][0], bf[p][1], bf[p][2], bf[p][3], bB + swz(bRowOff[p] + kbyte));
#pragma unroll
            for (int mt = 0; mt < 4; mt++) {
#pragma unroll
                for (int p = 0; p < 2; p++) {
                    mma_fp16(acc[mt][2*p][0], acc[mt][2*p][1], acc[mt][2*p][2], acc[mt][2*p][3],
                             af[mt][0], af[mt][1], af[mt][2], af[mt][3], bf[p][0], bf[p][1]);
                    mma_fp16(acc[mt][2*p+1][0], acc[mt][2*p+1][1], acc[mt][2*p+1][2], acc[mt][2*p+1][3],
                             af[mt][0], af[mt][1], af[mt][2], af[mt][3], bf[p][2], bf[p][3]);
                }
            }
        }
    }

    if (OMODE == 2) {
        // ---- RoPE epilogue: stage acc tile to smem, rotate pairs (d, d+64) ----
        float* Sacc = (float*)(dynsmem + (base - smem_u32(dynsmem)));
        __syncthreads();   // everyone done with stage buffers
#pragma unroll
        for (int mt = 0; mt < 4; mt++) {
            int rt = wm * 64 + mt * 16 + grp;
#pragma unroll
            for (int nt = 0; nt < 4; nt++) {
                int ct = wn * 32 + nt * 8 + 2 * tig;
                Sacc[rt * 132 + ct]           = acc[mt][nt][0];
                Sacc[rt * 132 + ct + 1]       = acc[mt][nt][1];
                Sacc[(rt + 8) * 132 + ct]     = acc[mt][nt][2];
                Sacc[(rt + 8) * 132 + ct + 1] = acc[mt][nt][3];
            }
        }
        __syncthreads();
        int row = tid >> 1;
        int d0  = (tid & 1) * 32;
        int m   = m0 + row;
        int s   = m & (SS - 1);
        const float* cr = cosT + (size_t)s * HD;
        const float* sr = sinT + (size_t)s * HD;
        __half* dst = (__half*)Cv + ((size_t)m * nheads + blockIdx.y) * HD;
#pragma unroll
        for (int j = 0; j < 32; j += 2) {
            int d = d0 + j;
            float a1a = Sacc[row * 132 + d],      a1b = Sacc[row * 132 + d + 1];
            float a2a = Sacc[row * 132 + d + 64], a2b = Sacc[row * 132 + d + 65];
            float c0 = cr[d], c1 = cr[d + 1];
            float s0 = sr[d], s1 = sr[d + 1];
            *(__half2*)(dst + d)      = __floats2half2_rn(a1a * c0 - a2a * s0, a1b * c1 - a2b * s1);
            *(__half2*)(dst + d + 64) = __floats2half2_rn(a2a * c0 + a1a * s0, a2b * c1 + a1b * s1);
        }
    } else {
#pragma unroll
        for (int mt = 0; mt < 4; mt++) {
            int rbase = m0 + wm * 64 + mt * 16 + grp;
#pragma unroll
            for (int nt = 0; nt < 4; nt++) {
                int col = n0 + wn * 32 + nt * 8 + 2 * tig;
                if (OMODE == 1) {
                    __half* C = (__half*)Cv;
                    *(__half2*)(C + (size_t)rbase * N + col)       = __floats2half2_rn(acc[mt][nt][0], acc[mt][nt][1]);
                    *(__half2*)(C + (size_t)(rbase + 8) * N + col) = __floats2half2_rn(acc[mt][nt][2], acc[mt][nt][3]);
                } else {
                    float* C = (float*)Cv;
                    float* d0p = C + (size_t)rbase * N + col;
                    float* d1p = C + (size_t)(rbase + 8) * N + col;
                    d0p[0] = acc[mt][nt][0]; d0p[1] = acc[mt][nt][1];
                    d1p[0] = acc[mt][nt][2]; d1p[1] = acc[mt][nt][3];
                }
            }
        }
    }
}

// ---------------------------------------------------------------------------
// FP16 tensor-core flash attention, sliding window, GQA.
// ---------------------------------------------------------------------------
#define AT_QBYTES 16384
#define AT_KVBUF  32768
#define AT_OFF_KV AT_QBYTES
#define AT_OFF_RED  (AT_OFF_KV + 2*AT_KVBUF)
#define AT_OFF_RED2 (AT_OFF_RED + 64*2*4)
#define AT_SMEM     (AT_OFF_RED2 + 64*2*4)            // 82944
#define OB_STRIDE 132

__device__ __forceinline__ void at_load_q(uint32_t qBase, const __half* __restrict__ Qg,
                                          int b, int q0, int h, int tid) {
#pragma unroll
    for (int i = 0; i < 4; i++) {
        int id = tid + i * 256;
        int row = id >> 4, u = id & 15;
        int ch = u >> 3, c16 = u & 7;
        const __half* src = Qg + ((size_t)(b * SS + q0 + row) * NH + h) * HD + ch * 64 + c16 * 8;
        cp16(qBase + ch * 8192 + swz((uint32_t)(row * 128 + c16 * 16)), src);
    }
}
__device__ __forceinline__ void at_load_kv(uint32_t kvBase, const __half* __restrict__ Kg,
                                           const __half* __restrict__ Vg,
                                           int b, int k0, int kvh, int tid) {
#pragma unroll
    for (int i = 0; i < 8; i++) {
        int id = tid + i * 256;
        int isV = id >= 1024;
        int cid = id & 1023;
        int row = cid >> 4, u = cid & 15;
        int ch = u >> 3, c16 = u & 7;
        const __half* src = (isV ? Vg : Kg) +
            ((size_t)(b * SS + k0 + row) * NKV + kvh) * HD + ch * 64 + c16 * 8;
        cp16(kvBase + (isV ? 16384 : 0) + ch * 8192 + swz((uint32_t)(row * 128 + c16 * 16)), src);
    }
}

__global__ __launch_bounds__(256, 2) void attn_mma_kernel(
    const __half* __restrict__ Q, const __half* __restrict__ K,
    const __half* __restrict__ V, __half* __restrict__ O)
{
    extern __shared__ char smc[];
    const uint32_t sb = smem_u32(smc);
    float* red  = (float*)(smc + AT_OFF_RED);
    float* red2 = (float*)(smc + AT_OFF_RED2);

    const int tid = threadIdx.x;
    const int w = tid >> 5, lane = tid & 31;
    const int grp = lane >> 2, tl = lane & 3;
    const int t8 = lane & 7, which = lane >> 3;
    const int wr = w & 3, wc = w >> 2;
    const int qb = blockIdx.x, h = blockIdx.y, b = blockIdx.z;
    const int kvh = h >> 2;
    const int q0 = qb * 64;
    const int grow = wr * 16 + grp;
    const float scl = 0.08838834764831845f;

    const uint32_t qoff = (uint32_t)((wr * 16 + (which & 1) * 8 + t8) * 128 + (which >> 1) * 16);
    uint32_t koff[2], voff[2];
#pragma unroll
    for (int p = 0; p < 2; p++)
        koff[p] = (uint32_t)((wc * 32 + p * 16 + (which >> 1) * 8 + t8) * 128 + (which & 1) * 16);
#pragma unroll
    for (int ks = 0; ks < 2; ks++)
        voff[ks] = (uint32_t)((wc * 32 + ks * 16 + (which & 1) * 8 + t8) * 128 + (which >> 1) * 16);

    float m1 = -1e30f, m2 = -1e30f, l1 = 0.f, l2 = 0.f;
    float oacc[16][4];
#pragma unroll
    for (int t = 0; t < 16; t++)
#pragma unroll
        for (int e = 0; e < 4; e++) oacc[t][e] = 0.f;

    const int kb_lo = (qb >= 16) ? (qb - 16) : 0;

    at_load_q(sb, Q, b, q0, h, tid);
    at_load_kv(sb + AT_OFF_KV, K, V, b, kb_lo * 64, kvh, tid);
    asm volatile("cp.async.commit_group;" ::: "memory");

    for (int kb = kb_lo; kb <= qb; kb++) {
        const int cur = (kb - kb_lo) & 1;
        const int k0 = kb * 64;
        const uint32_t kvB = sb + AT_OFF_KV + cur * AT_KVBUF;

        __syncthreads();
        if (kb < qb) {
            at_load_kv(sb + AT_OFF_KV + (cur ^ 1) * AT_KVBUF, K, V, b, k0 + 64, kvh, tid);
            asm volatile("cp.async.commit_group;" ::: "memory");
            asm volatile("cp.async.wait_group 1;" ::: "memory");
        } else {
            asm volatile("cp.async.wait_group 0;" ::: "memory");
        }
        __syncthreads();

        float sacc[4][4];
#pragma unroll
        for (int nt = 0; nt < 4; nt++)
#pragma unroll
            for (int e = 0; e < 4; e++) sacc[nt][e] = 0.f;

#pragma unroll
        for (int c = 0; c < 2; c++) {
            uint32_t qB = sb + c * 8192;
            uint32_t kB = kvB + c * 8192;
#pragma unroll
            for (int ks = 0; ks < 4; ks++) {
                uint32_t kbyte = (uint32_t)(ks * 32);
                uint32_t af[4], bf[2][4];
                ldsm4(af[0], af[1], af[2], af[3], qB + swz(qoff + kbyte));
#pragma unroll
                for (int p = 0; p < 2; p++)
                    ldsm4(bf[p][0], bf[p][1], bf[p][2], bf[p][3], kB + swz(koff[p] + kbyte));
#pragma unroll
                for (int p = 0; p < 2; p++) {
                    mma_fp16(sacc[2*p][0], sacc[2*p][1], sacc[2*p][2], sacc[2*p][3],
                             af[0], af[1], af[2], af[3], bf[p][0], bf[p][1]);
                    mma_fp16(sacc[2*p+1][0], sacc[2*p+1][1], sacc[2*p+1][2], sacc[2*p+1][3],
                             af[0], af[1], af[2], af[3], bf[p][2], bf[p][3]);
                }
            }
        }

#pragma unroll
        for (int nt = 0; nt < 4; nt++)
#pragma unroll
            for (int e = 0; e < 4; e++) sacc[nt][e] *= scl;

        if (kb == qb || qb - kb == 16) {
            int r0g = q0 + grow;
#pragma unroll
            for (int nt = 0; nt < 4; nt++) {
                int cbase = k0 + wc * 32 + nt * 8 + 2 * tl;
#pragma unroll
                for (int e = 0; e < 4; e++) {
                    int gi = r0g + (e >> 1) * 8;
                    int gj = cbase + (e & 1);
                    int dist = gi - gj;
                    if (!(dist >= 0 && dist < WINDOW)) sacc[nt][e] = -1e30f;
                }
            }
        }

        float mx1 = -1e30f, mx2 = -1e30f;
#pragma unroll
        for (int nt = 0; nt < 4; nt++) {
            mx1 = fmaxf(mx1, fmaxf(sacc[nt][0], sacc[nt][1]));
            mx2 = fmaxf(mx2, fmaxf(sacc[nt][2], sacc[nt][3]));
        }
        mx1 = fmaxf(mx1, __shfl_xor_sync(0xffffffffu, mx1, 1));
        mx1 = fmaxf(mx1, __shfl_xor_sync(0xffffffffu, mx1, 2));
        mx2 = fmaxf(mx2, __shfl_xor_sync(0xffffffffu, mx2, 1));
        mx2 = fmaxf(mx2, __shfl_xor_sync(0xffffffffu, mx2, 2));
        if (tl == 0) {
            red[grow * 2 + wc]       = mx1;
            red[(grow + 8) * 2 + wc] = mx2;
        }
        __syncthreads();

        float mn1 = fmaxf(m1, fmaxf(red[grow * 2], red[grow * 2 + 1]));
        float mn2 = fmaxf(m2, fmaxf(red[(grow + 8) * 2], red[(grow + 8) * 2 + 1]));
        float f1 = __expf(m1 - mn1);
        float f2 = __expf(m2 - mn2);
        m1 = mn1; m2 = mn2;

        float s1 = 0.f, s2 = 0.f;
        uint32_t ph[4][2];
#pragma unroll
        for (int nt = 0; nt < 4; nt++) {
            float p0 = __expf(sacc[nt][0] - mn1);
            float p1 = __expf(sacc[nt][1] - mn1);
            float p2 = __expf(sacc[nt][2] - mn2);
            float p3 = __expf(sacc[nt][3] - mn2);
            s1 += p0 + p1; s2 += p2 + p3;
            ph[nt][0] = packh2(p0, p1);
            ph[nt][1] = packh2(p2, p3);
        }
        s1 += __shfl_xor_sync(0xffffffffu, s1, 1);
        s1 += __shfl_xor_sync(0xffffffffu, s1, 2);
        s2 += __shfl_xor_sync(0xffffffffu, s2, 1);
        s2 += __shfl_xor_sync(0xffffffffu, s2, 2);
        if (tl == 0) {
            red2[grow * 2 + wc]       = s1;
            red2[(grow + 8) * 2 + wc] = s2;
        }
#pragma unroll
        for (int t = 0; t < 16; t++) {
            oacc[t][0] *= f1; oacc[t][1] *= f1;
            oacc[t][2] *= f2; oacc[t][3] *= f2;
        }
        __syncthreads();
        l1 = l1 * f1 + red2[grow * 2] + red2[grow * 2 + 1];
        l2 = l2 * f2 + red2[(grow + 8) * 2] + red2[(grow + 8) * 2 + 1];

#pragma unroll
        for (int c = 0; c < 2; c++) {
            uint32_t vB = kvB + 16384 + c * 8192;
#pragma unroll
            for (int db = 0; db < 4; db++) {
#pragma unroll
                for (int ks = 0; ks < 2; ks++) {
                    uint32_t bf0, bf1, bf2, bf3;
                    ldsm4t(bf0, bf1, bf2, bf3, vB + swz(voff[ks] + (uint32_t)(db * 32)));
                    int tlo = (c * 4 + db) * 2, thi = tlo + 1;
                    mma_fp16(oacc[tlo][0], oacc[tlo][1], oacc[tlo][2], oacc[tlo][3],
                             ph[2*ks][0], ph[2*ks][1], ph[2*ks+1][0], ph[2*ks+1][1],
                             bf0, bf1);
                    mma_fp16(oacc[thi][0], oacc[thi][1], oacc[thi][2], oacc[thi][3],
                             ph[2*ks][0], ph[2*ks][1], ph[2*ks+1][0], ph[2*ks+1][1],
                             bf2, bf3);
                }
            }
        }
    }

    __syncthreads();
    float* Obuf = (float*)(smc + AT_OFF_KV);
    if (wc == 0) {
#pragma unroll
        for (int t = 0; t < 16; t++) {
            int d = (t >> 3) * 64 + ((t >> 1) & 3) * 16 + (t & 1) * 8 + 2 * tl;
            *(float2*)&Obuf[grow * OB_STRIDE + d]       = make_float2(oacc[t][0], oacc[t][1]);
            *(float2*)&Obuf[(grow + 8) * OB_STRIDE + d] = make_float2(oacc[t][2], oacc[t][3]);
        }
    }
    __syncthreads();
    if (wc == 1) {
        float inv1 = 1.0f / l1;
        float inv2 = 1.0f / l2;
        __half* dst1 = O + ((size_t)(b * SS + q0 + grow) * NH + h) * HD;
        __half* dst2 = O + ((size_t)(b * SS + q0 + grow + 8) * NH + h) * HD;
#pragma unroll
        for (int t = 0; t < 16; t++) {
            int d = (t >> 3) * 64 + ((t >> 1) & 3) * 16 + (t & 1) * 8 + 2 * tl;
            float2 p1 = *(float2*)&Obuf[grow * OB_STRIDE + d];
            float2 p2 = *(float2*)&Obuf[(grow + 8) * OB_STRIDE + d];
            *(__half2*)(dst1 + d) = __floats2half2_rn((p1.x + oacc[t][0]) * inv1,
                                                      (p1.y + oacc[t][1]) * inv1);
            *(__half2*)(dst2 + d) = __floats2half2_rn((p2.x + oacc[t][2]) * inv2,
                                                      (p2.y + oacc[t][3]) * inv2);
        }
    }
}

// ---------------------------------------------------------------------------
// Launch
// ---------------------------------------------------------------------------
extern "C" void kernel_launch(void* const* d_in, const int* in_sizes, int n_in,
                              void* d_out, int out_size)
{
    const float* x    = (const float*)d_in[0];
    const float* cosT = (const float*)d_in[1];
    const float* sinT = (const float*)d_in[2];
    const float* Wq   = (const float*)d_in[3];
    const float* Wk   = (const float*)d_in[4];
    const float* Wv   = (const float*)d_in[5];
    const float* Wo   = (const float*)d_in[6];
    float* out = (float*)d_out;

    void *pQh, *pKh, *pVh, *pA, *pXh, *pWq, *pWk, *pWv, *pWo;
    cudaGetSymbolAddress(&pQh, g_Qh);
    cudaGetSymbolAddress(&pKh, g_Kh);
    cudaGetSymbolAddress(&pVh, g_Vh);
    cudaGetSymbolAddress(&pA, g_Aoh);
    cudaGetSymbolAddress(&pXh, g_Xh);
    cudaGetSymbolAddress(&pWq, g_Wqh);
    cudaGetSymbolAddress(&pWk, g_Wkh);
    cudaGetSymbolAddress(&pWv, g_Wvh);
    cudaGetSymbolAddress(&pWo, g_Woh);
    __half* Qh = (__half*)pQh;  __half* Kh = (__half*)pKh;
    __half* Vh = (__half*)pVh;  __half* Ah = (__half*)pA;
    __half* Xh = (__half*)pXh;
    __half* Wqh = (__half*)pWq; __half* Wkh = (__half*)pWk;
    __half* Wvh = (__half*)pWv; __half* Woh = (__half*)pWo;

    // Convert inputs to fp16
    conv_fp16_kernel<<<(MROWS * EE / 4) / 256, 256>>>(x, Xh);
    conv_fp16_kernel<<<(NH * HD * EE / 4) / 256, 256>>>(Wq, Wqh);
    conv_fp16_kernel<<<(NKV * HD * EE / 4) / 256, 256>>>(Wk, Wkh);
    conv_fp16_kernel<<<(NKV * HD * EE / 4) / 256, 256>>>(Wv, Wvh);
    conv_fp16_kernel<<<(EE * EE / 4) / 256, 256>>>(Wo, Woh);

    // Projections (Q/K with fused RoPE -> fp16; V -> fp16; O-proj -> fp32)
    cudaFuncSetAttribute(gemm_fp16<0>, cudaFuncAttributeMaxDynamicSharedMemorySize, GEMM_DYN);
    cudaFuncSetAttribute(gemm_fp16<1>, cudaFuncAttributeMaxDynamicSharedMemorySize, GEMM_DYN);
    cudaFuncSetAttribute(gemm_fp16<2>, cudaFuncAttributeMaxDynamicSharedMemorySize, GEMM_DYN);
    gemm_fp16<2><<<dim3(MROWS / TM, (NH  * HD) / TN), 256, GEMM_DYN>>>(Xh, Wqh, Qh, NH  * HD, EE, cosT, sinT, NH);
    gemm_fp16<2><<<dim3(MROWS / TM, (NKV * HD) / TN), 256, GEMM_DYN>>>(Xh, Wkh, Kh, NKV * HD, EE, cosT, sinT, NKV);
    gemm_fp16<1><<<dim3(MROWS / TM, (NKV * HD) / TN), 256, GEMM_DYN>>>(Xh, Wvh, Vh, NKV * HD, EE, nullptr, nullptr, 0);

    // Attention (fp16 tensor cores)
    cudaFuncSetAttribute(attn_mma_kernel, cudaFuncAttributeMaxDynamicSharedMemorySize, AT_SMEM);
    attn_mma_kernel<<<dim3(SS / 64, NH, BB), 256, AT_SMEM>>>(Qh, Kh, Vh, Ah);

    // Output projection
    gemm_fp16<0><<<dim3(MROWS / TM, EE / TN), 256, GEMM_DYN>>>(Ah, Woh, out, EE, EE, nullptr, nullptr, 0);
}